// round 2
// baseline (speedup 1.0000x reference)
#include <cuda_runtime.h>
#include <cstdint>
#include <cstddef>

// ---------------------------------------------------------------------------
// Problem constants
// ---------------------------------------------------------------------------
#define NB    32          // batch
#define NPIX  4096        // H*W = 64*64
#define NTOK  (NB*NPIX)   // 131072 tokens
#define CIN   960
#define C3    96          // qkv channels
#define NG    12          // attention groups
#define HW    64

// ---------------------------------------------------------------------------
// Scratch (device globals: no cudaMalloc allowed)
// ---------------------------------------------------------------------------
__device__ float g_stats[(size_t)NTOK * 6];                 // mean[3], rstd[3] per token (3 MB)
__device__ float g_multi[(size_t)NB * 288 * NPIX];          // [b][ch][n], ch: 0-95 qkv, 96-191 m3, 192-287 m5 (151 MB)
__device__ float g_att[(size_t)NB * C3 * NPIX];             // [b][ch][n] (50 MB)

// ---------------------------------------------------------------------------
// K1: per-token LayerNorm stats (mean, rstd) for the 3 segments
// One warp per token.
// ---------------------------------------------------------------------------
__global__ void ln_stats_kernel(const float* __restrict__ x1,
                                const float* __restrict__ x2,
                                const float* __restrict__ x3) {
    int warp = (blockIdx.x * blockDim.x + threadIdx.x) >> 5;   // token id
    int lane = threadIdx.x & 31;
    if (warp >= NTOK) return;
    const float* xs[3] = {x1, x2, x3};
    const int    Cs[3] = {192, 256, 512};
    #pragma unroll
    for (int s = 0; s < 3; s++) {
        const float* p = xs[s] + (size_t)warp * Cs[s];
        float sum = 0.f, sq = 0.f;
        for (int c = lane; c < Cs[s]; c += 32) { float v = p[c]; sum += v; sq += v * v; }
        #pragma unroll
        for (int off = 16; off > 0; off >>= 1) {
            sum += __shfl_xor_sync(0xffffffffu, sum, off);
            sq  += __shfl_xor_sync(0xffffffffu, sq,  off);
        }
        if (lane == 0) {
            float m   = sum / (float)Cs[s];
            float var = sq / (float)Cs[s] - m * m;
            g_stats[(size_t)warp * 6 + s]     = m;
            g_stats[(size_t)warp * 6 + 3 + s] = rsqrtf(var + 1e-6f);
        }
    }
}

// ---------------------------------------------------------------------------
// K2: qkv = LN(x_cat) @ qkv_w^T   (M=131072, N=96, K=960)
// Block: 128 tokens x 96 outs, K-tile 32 (tiles align with segment bounds).
// LN applied on-the-fly in the A-tile loader. Output written channel-major
// into g_multi via float4 (8 consecutive tokens per out).
// ---------------------------------------------------------------------------
__global__ void __launch_bounds__(256) qkv_gemm_kernel(
    const float* __restrict__ x1, const float* __restrict__ x2, const float* __restrict__ x3,
    const float* __restrict__ g1, const float* __restrict__ b1,
    const float* __restrict__ g2, const float* __restrict__ b2,
    const float* __restrict__ g3, const float* __restrict__ b3,
    const float* __restrict__ qkv_w) {
    __shared__ float As[128][33];   // [token][k]
    __shared__ float Ws[32][96];    // [k][o]
    const int tid = threadIdx.x;
    const int tx = tid & 15, ty = tid >> 4;
    const int token0 = blockIdx.x * 128;

    float acc[8][6];
    #pragma unroll
    for (int i = 0; i < 8; i++)
        #pragma unroll
        for (int j = 0; j < 6; j++) acc[i][j] = 0.f;

    for (int kt = 0; kt < 30; kt++) {
        const int k0 = kt * 32;
        int seg, cbase, Csz; const float *xp, *gp, *bp;
        if (k0 < 192)      { seg = 0; cbase = 0;   Csz = 192; xp = x1; gp = g1; bp = b1; }
        else if (k0 < 448) { seg = 1; cbase = 192; Csz = 256; xp = x2; gp = g2; bp = b2; }
        else               { seg = 2; cbase = 448; Csz = 512; xp = x3; gp = g3; bp = b3; }
        __syncthreads();
        // A tile: 128x32, normalized while loading
        #pragma unroll
        for (int l = 0; l < 4; l++) {
            int fid = tid + l * 256;
            int row = fid >> 3, q4 = fid & 7;
            int token = token0 + row;
            int cl = k0 - cbase + q4 * 4;
            float4 xv = *reinterpret_cast<const float4*>(xp + (size_t)token * Csz + cl);
            float4 gv = *reinterpret_cast<const float4*>(gp + cl);
            float4 bv = *reinterpret_cast<const float4*>(bp + cl);
            float m = g_stats[(size_t)token * 6 + seg];
            float r = g_stats[(size_t)token * 6 + 3 + seg];
            As[row][q4 * 4 + 0] = (xv.x - m) * (r * gv.x) + bv.x;
            As[row][q4 * 4 + 1] = (xv.y - m) * (r * gv.y) + bv.y;
            As[row][q4 * 4 + 2] = (xv.z - m) * (r * gv.z) + bv.z;
            As[row][q4 * 4 + 3] = (xv.w - m) * (r * gv.w) + bv.w;
        }
        // W tile: 96x32 transposed into [k][o]
        #pragma unroll
        for (int l = 0; l < 3; l++) {
            int idx4 = tid + l * 256;
            int o = idx4 >> 3, k4 = idx4 & 7;
            float4 wv = *reinterpret_cast<const float4*>(qkv_w + (size_t)o * 960 + k0 + k4 * 4);
            Ws[k4 * 4 + 0][o] = wv.x;
            Ws[k4 * 4 + 1][o] = wv.y;
            Ws[k4 * 4 + 2][o] = wv.z;
            Ws[k4 * 4 + 3][o] = wv.w;
        }
        __syncthreads();
        #pragma unroll 8
        for (int kk = 0; kk < 32; kk++) {
            float av[8], wv[6];
            #pragma unroll
            for (int i = 0; i < 8; i++) av[i] = As[ty * 8 + i][kk];
            #pragma unroll
            for (int j = 0; j < 6; j++) wv[j] = Ws[kk][tx + 16 * j];
            #pragma unroll
            for (int i = 0; i < 8; i++)
                #pragma unroll
                for (int j = 0; j < 6; j++) acc[i][j] = fmaf(av[i], wv[j], acc[i][j]);
        }
    }
    const int b  = token0 >> 12;
    const int n0 = token0 & (NPIX - 1);
    #pragma unroll
    for (int j = 0; j < 6; j++) {
        int o = tx + 16 * j;
        float* dst = g_multi + ((size_t)b * 288 + o) * NPIX + n0 + ty * 8;
        float4 v0 = make_float4(acc[0][j], acc[1][j], acc[2][j], acc[3][j]);
        float4 v1 = make_float4(acc[4][j], acc[5][j], acc[6][j], acc[7][j]);
        *reinterpret_cast<float4*>(dst)     = v0;
        *reinterpret_cast<float4*>(dst + 4) = v1;
    }
}

// ---------------------------------------------------------------------------
// K3/K4: fused depthwise KxK conv + grouped 8x8 pointwise, per (b, group, 32x32 tile)
// input:  g_multi channels [g*8, g*8+8)   (qkv)
// output: g_multi channels [out_ch_base + g*8, ... +8)
// ---------------------------------------------------------------------------
template<int K>
__global__ void __launch_bounds__(256) dwpw_kernel(const float* __restrict__ dw_w,
                                                   const float* __restrict__ pw_w,
                                                   int out_ch_base) {
    constexpr int R = K / 2;
    constexpr int T = 32 + 2 * R;
    __shared__ float sin_[8][T][T];
    __shared__ float wdw[8][K * K];
    __shared__ float wpw[8][8];
    const int b = blockIdx.z, g = blockIdx.y, tile = blockIdx.x;
    const int ty0 = (tile >> 1) * 32, tx0 = (tile & 1) * 32;
    const int tid = threadIdx.x;
    const float* src = g_multi + ((size_t)b * 288 + g * 8) * NPIX;

    for (int idx = tid; idx < 8 * T * T; idx += 256) {
        int ch = idx / (T * T); int rem = idx - ch * T * T;
        int yy = rem / T, xx = rem - yy * T;
        int gy = ty0 + yy - R, gx = tx0 + xx - R;
        float v = 0.f;
        if (gy >= 0 && gy < HW && gx >= 0 && gx < HW) v = src[ch * NPIX + gy * HW + gx];
        sin_[ch][yy][xx] = v;
    }
    if (tid < 8 * K * K) {
        int ch = tid / (K * K); int kk = tid - ch * (K * K);
        wdw[ch][kk] = dw_w[(g * 8 + ch) * (K * K) + kk];
    }
    if (tid < 64) wpw[tid >> 3][tid & 7] = pw_w[(g * 8 + (tid >> 3)) * 8 + (tid & 7)];
    __syncthreads();

    float* dst = g_multi + ((size_t)b * 288 + out_ch_base + g * 8) * NPIX;
    #pragma unroll
    for (int pp = 0; pp < 4; pp++) {
        int p = tid + pp * 256;
        int py = p >> 5, px = p & 31;
        float d[8];
        #pragma unroll
        for (int ch = 0; ch < 8; ch++) {
            float s = 0.f;
            #pragma unroll
            for (int ky = 0; ky < K; ky++)
                #pragma unroll
                for (int kx = 0; kx < K; kx++)
                    s = fmaf(sin_[ch][py + ky][px + kx], wdw[ch][ky * K + kx], s);
            d[ch] = s;
        }
        int n = (ty0 + py) * HW + (tx0 + px);
        #pragma unroll
        for (int o = 0; o < 8; o++) {
            float s = 0.f;
            #pragma unroll
            for (int i = 0; i < 8; i++) s = fmaf(wpw[o][i], d[i], s);
            dst[o * NPIX + n] = s;
        }
    }
}

// ---------------------------------------------------------------------------
// K5: linear attention per (b, g). Phase 1: vk[9][8] = sum_n [v;1] k^T (relu k).
//     Phase 2: att[d][n] = (sum_e vk[d][e] relu(q[e][n])) / (den + 1e-15).
// ---------------------------------------------------------------------------
__global__ void __launch_bounds__(256) attn_kernel() {
    const int g = blockIdx.x, b = blockIdx.y;
    const int tid = threadIdx.x, lane = tid & 31, wrp = tid >> 5;
    const float* mg = g_multi + ((size_t)b * 288 + g * 24) * NPIX;  // q:+0, k:+8*N, v:+16*N

    float acc[9][8];
    #pragma unroll
    for (int d = 0; d < 9; d++)
        #pragma unroll
        for (int e = 0; e < 8; e++) acc[d][e] = 0.f;

    for (int n = tid; n < NPIX; n += 256) {
        float kv[8], vv[8];
        #pragma unroll
        for (int e = 0; e < 8; e++) kv[e] = fmaxf(mg[(8 + e) * NPIX + n], 0.f);
        #pragma unroll
        for (int d = 0; d < 8; d++) vv[d] = mg[(16 + d) * NPIX + n];
        #pragma unroll
        for (int d = 0; d < 8; d++)
            #pragma unroll
            for (int e = 0; e < 8; e++) acc[d][e] = fmaf(vv[d], kv[e], acc[d][e]);
        #pragma unroll
        for (int e = 0; e < 8; e++) acc[8][e] += kv[e];
    }
    __shared__ float red[8][72];
    __shared__ float vk[72];
    #pragma unroll
    for (int d = 0; d < 9; d++)
        #pragma unroll
        for (int e = 0; e < 8; e++) {
            float s = acc[d][e];
            #pragma unroll
            for (int off = 16; off > 0; off >>= 1) s += __shfl_xor_sync(0xffffffffu, s, off);
            if (lane == 0) red[wrp][d * 8 + e] = s;
        }
    __syncthreads();
    if (tid < 72) {
        float s = 0.f;
        #pragma unroll
        for (int w = 0; w < 8; w++) s += red[w][tid];
        vk[tid] = s;
    }
    __syncthreads();

    float* ab = g_att + ((size_t)b * C3 + g * 8) * NPIX;
    for (int n = tid; n < NPIX; n += 256) {
        float num[8];
        #pragma unroll
        for (int d = 0; d < 8; d++) num[d] = 0.f;
        float den = 1e-15f;
        #pragma unroll
        for (int e = 0; e < 8; e++) {
            float q = fmaxf(mg[e * NPIX + n], 0.f);
            #pragma unroll
            for (int d = 0; d < 8; d++) num[d] = fmaf(vk[d * 8 + e], q, num[d]);
            den = fmaf(vk[64 + e], q, den);
        }
        float inv = 1.f / den;
        #pragma unroll
        for (int d = 0; d < 8; d++) ab[d * NPIX + n] = num[d] * inv;
    }
}

// ---------------------------------------------------------------------------
// K6: out = att @ proj_w^T (M=131072, N=960, K=96) + BN + residual + 3-way split
// Block: 128 tokens x 96 outs; K fully looped (3 tiles of 32).
// ---------------------------------------------------------------------------
__global__ void __launch_bounds__(256) proj_gemm_kernel(
    const float* __restrict__ proj_w,
    const float* __restrict__ bn_g, const float* __restrict__ bn_b,
    const float* __restrict__ bn_m, const float* __restrict__ bn_v,
    const float* __restrict__ x1, const float* __restrict__ x2, const float* __restrict__ x3,
    float* __restrict__ out) {
    __shared__ float As[32][129];   // [k][token]
    __shared__ float Ws[32][96];    // [k][o]
    const int tid = threadIdx.x;
    const int tx = tid & 15, ty = tid >> 4;
    const int token0 = blockIdx.x * 128;
    const int o0 = blockIdx.y * 96;
    const int b  = token0 >> 12;
    const int n0 = token0 & (NPIX - 1);
    const float* attb = g_att + (size_t)b * C3 * NPIX;

    float acc[8][6];
    #pragma unroll
    for (int i = 0; i < 8; i++)
        #pragma unroll
        for (int j = 0; j < 6; j++) acc[i][j] = 0.f;

    for (int kt = 0; kt < 3; kt++) {
        const int k0 = kt * 32;
        __syncthreads();
        #pragma unroll
        for (int l = 0; l < 4; l++) {
            int idx4 = tid + l * 256;
            int kk = idx4 >> 5, t4 = idx4 & 31;
            float4 v = *reinterpret_cast<const float4*>(attb + (size_t)(k0 + kk) * NPIX + n0 + t4 * 4);
            As[kk][t4 * 4 + 0] = v.x;
            As[kk][t4 * 4 + 1] = v.y;
            As[kk][t4 * 4 + 2] = v.z;
            As[kk][t4 * 4 + 3] = v.w;
        }
        #pragma unroll
        for (int l = 0; l < 3; l++) {
            int idx4 = tid + l * 256;
            int o = idx4 >> 3, k4 = idx4 & 7;
            float4 wv = *reinterpret_cast<const float4*>(proj_w + (size_t)(o0 + o) * 96 + k0 + k4 * 4);
            Ws[k4 * 4 + 0][o] = wv.x;
            Ws[k4 * 4 + 1][o] = wv.y;
            Ws[k4 * 4 + 2][o] = wv.z;
            Ws[k4 * 4 + 3][o] = wv.w;
        }
        __syncthreads();
        #pragma unroll 8
        for (int kk = 0; kk < 32; kk++) {
            float av[8], wv[6];
            #pragma unroll
            for (int i = 0; i < 8; i++) av[i] = As[kk][ty * 8 + i];
            #pragma unroll
            for (int j = 0; j < 6; j++) wv[j] = Ws[kk][tx + 16 * j];
            #pragma unroll
            for (int i = 0; i < 8; i++)
                #pragma unroll
                for (int j = 0; j < 6; j++) acc[i][j] = fmaf(av[i], wv[j], acc[i][j]);
        }
    }
    // Epilogue: BN affine + residual + split-write
    #pragma unroll
    for (int j = 0; j < 6; j++) {
        int o = o0 + tx + 16 * j;
        float sc = __ldg(bn_g + o) * rsqrtf(__ldg(bn_v + o) + 1e-5f);
        float sh = __ldg(bn_b + o) - __ldg(bn_m + o) * sc;
        const float* xr; size_t obase; int Csz, cl;
        if (o < 192)      { xr = x1; obase = 0;                        Csz = 192; cl = o; }
        else if (o < 448) { xr = x2; obase = (size_t)NTOK * 192;       Csz = 256; cl = o - 192; }
        else              { xr = x3; obase = (size_t)NTOK * 448;       Csz = 512; cl = o - 448; }
        #pragma unroll
        for (int i = 0; i < 8; i++) {
            int token = token0 + ty * 8 + i;
            size_t idx = (size_t)token * Csz + cl;
            out[obase + idx] = acc[i][j] * sc + sh + __ldg(xr + idx);
        }
    }
}

// ---------------------------------------------------------------------------
// Launch: classify inputs by element count (robust to metadata ordering;
// same-size ties use documented relative order).
// ---------------------------------------------------------------------------
extern "C" void kernel_launch(void* const* d_in, const int* in_sizes, int n_in,
                              void* d_out, int out_size) {
    (void)out_size;
    const float *x1 = 0, *x2 = 0, *x3 = 0;
    const float *g1 = 0, *b1 = 0, *g2 = 0, *b2 = 0, *g3 = 0, *b3 = 0;
    const float *qkv_w = 0, *dw3 = 0, *pw3 = 0, *dw5 = 0, *pw5 = 0, *proj_w = 0;
    const float *bn_g = 0, *bn_b = 0, *bn_m = 0, *bn_v = 0;
    int c192 = 0, c256 = 0, c512 = 0, cW = 0, c768 = 0, c960 = 0;
    for (int i = 0; i < n_in; i++) {
        const float* p = (const float*)d_in[i];
        switch (in_sizes[i]) {
            case 25165824: x1 = p; break;                      // 32*4096*192
            case 33554432: x2 = p; break;                      // 32*4096*256
            case 67108864: x3 = p; break;                      // 32*4096*512
            case 192: (c192++ ? b1 : g1) = p; break;
            case 256: (c256++ ? b2 : g2) = p; break;
            case 512: (c512++ ? b3 : g3) = p; break;
            case 92160: (cW++ ? proj_w : qkv_w) = p; break;    // 96*960 then 960*96
            case 864:  dw3 = p; break;                         // 96*9
            case 2400: dw5 = p; break;                         // 96*25
            case 768: (c768++ ? pw5 : pw3) = p; break;         // 96*8 each
            case 960: {
                if      (c960 == 0) bn_g = p;
                else if (c960 == 1) bn_b = p;
                else if (c960 == 2) bn_m = p;
                else                bn_v = p;
                c960++;
            } break;
            default: break;
        }
    }
    float* out = (float*)d_out;

    // one warp per token -> NTOK warps -> NTOK/8 blocks of 256 threads
    ln_stats_kernel<<<NTOK / 8, 256>>>(x1, x2, x3);
    qkv_gemm_kernel<<<NTOK / 128, 256>>>(x1, x2, x3, g1, b1, g2, b2, g3, b3, qkv_w);
    dwpw_kernel<3><<<dim3(4, NG, NB), 256>>>(dw3, pw3, 96);
    dwpw_kernel<5><<<dim3(4, NG, NB), 256>>>(dw5, pw5, 192);
    attn_kernel<<<dim3(NG, NB), 256>>>();
    proj_gemm_kernel<<<dim3(NTOK / 128, 10), 256>>>(proj_w, bn_g, bn_b, bn_m, bn_v,
                                                    x1, x2, x3, out);
}

// round 3
// speedup vs baseline: 2.0482x; 2.0482x over previous
#include <cuda_runtime.h>
#include <cuda_bf16.h>
#include <cstdint>
#include <cstddef>

// ---------------------------------------------------------------------------
// Problem constants
// ---------------------------------------------------------------------------
#define NB    32
#define NPIX  4096
#define NTOK  (NB*NPIX)   // 131072
#define CIN   960
#define C3    96
#define NG    12
#define HW    64

typedef __nv_bfloat16 bf16;

// ---------------------------------------------------------------------------
// Scratch (device globals)
// ---------------------------------------------------------------------------
__device__ float g_stats[(size_t)NTOK * 6];            // mean[3], rstd[3] per token
__device__ bf16  g_multi[(size_t)NB * 288 * NPIX];     // [b][ch][n] bf16 (75 MB)
__device__ bf16  g_att  [(size_t)NB * C3  * NPIX];     // [b][ch][n] bf16 (25 MB)
__device__ bf16  g_wqkv [C3 * CIN];                    // bf16 qkv weight
__device__ bf16  g_wproj[CIN * C3];                    // bf16 proj weight

// ---------------------------------------------------------------------------
// K0: weight conversion fp32 -> bf16
// ---------------------------------------------------------------------------
__global__ void prep_weights(const float* __restrict__ qkv_w,
                             const float* __restrict__ proj_w) {
    int i = blockIdx.x * 256 + threadIdx.x;
    if (i < C3 * CIN) {
        g_wqkv[i]  = __float2bfloat16(qkv_w[i]);
        g_wproj[i] = __float2bfloat16(proj_w[i]);
    }
}

// ---------------------------------------------------------------------------
// K1: per-token LayerNorm stats (one warp per token)
// ---------------------------------------------------------------------------
__global__ void ln_stats_kernel(const float* __restrict__ x1,
                                const float* __restrict__ x2,
                                const float* __restrict__ x3) {
    int warp = (blockIdx.x * blockDim.x + threadIdx.x) >> 5;
    int lane = threadIdx.x & 31;
    if (warp >= NTOK) return;
    const float* xs[3] = {x1, x2, x3};
    const int    Cs[3] = {192, 256, 512};
    #pragma unroll
    for (int s = 0; s < 3; s++) {
        const float* p = xs[s] + (size_t)warp * Cs[s];
        float sum = 0.f, sq = 0.f;
        for (int c = lane; c < Cs[s]; c += 32) { float v = p[c]; sum += v; sq += v * v; }
        #pragma unroll
        for (int off = 16; off > 0; off >>= 1) {
            sum += __shfl_xor_sync(0xffffffffu, sum, off);
            sq  += __shfl_xor_sync(0xffffffffu, sq,  off);
        }
        if (lane == 0) {
            float m   = sum / (float)Cs[s];
            float var = sq / (float)Cs[s] - m * m;
            g_stats[(size_t)warp * 6 + s]     = m;
            g_stats[(size_t)warp * 6 + 3 + s] = rsqrtf(var + 1e-6f);
        }
    }
}

// ---------------------------------------------------------------------------
// mma.sync m16n8k16 bf16 helper
// ---------------------------------------------------------------------------
__device__ __forceinline__ void mma_bf16(float* c, const uint32_t* a, const uint32_t* b) {
    asm volatile(
        "mma.sync.aligned.m16n8k16.row.col.f32.bf16.bf16.f32 "
        "{%0,%1,%2,%3}, {%4,%5,%6,%7}, {%8,%9}, {%0,%1,%2,%3};\n"
        : "+f"(c[0]), "+f"(c[1]), "+f"(c[2]), "+f"(c[3])
        : "r"(a[0]), "r"(a[1]), "r"(a[2]), "r"(a[3]), "r"(b[0]), "r"(b[1]));
}

// ---------------------------------------------------------------------------
// K2: qkv GEMM (M=131072, N=96, K=960) with fused LN, bf16 tensor cores.
// Block: 128 tokens x 96 outs, 8 warps (4M x 2N), warp tile 32x48.
// ---------------------------------------------------------------------------
__global__ void __launch_bounds__(256) qkv_gemm_kernel(
    const float* __restrict__ x1, const float* __restrict__ x2, const float* __restrict__ x3,
    const float* __restrict__ g1, const float* __restrict__ b1,
    const float* __restrict__ g2, const float* __restrict__ b2,
    const float* __restrict__ g3, const float* __restrict__ b3) {
    __shared__ union {
        struct { bf16 A[128][40]; bf16 W[96][40]; } s;   // 17920 B
        bf16 C[96][136];                                  // 26112 B
    } sm;
    const int tid  = threadIdx.x;
    const int warp = tid >> 5, lane = tid & 31;
    const int warpM = warp & 3, warpN = warp >> 2;
    const int g = lane >> 2, tg = lane & 3;
    const int token0 = blockIdx.x * 128;

    float acc[2][6][4];
    #pragma unroll
    for (int mr = 0; mr < 2; mr++)
        #pragma unroll
        for (int nb = 0; nb < 6; nb++)
            #pragma unroll
            for (int q = 0; q < 4; q++) acc[mr][nb][q] = 0.f;

    for (int kt = 0; kt < 30; kt++) {
        const int k0 = kt * 32;
        int seg, cbase, Csz; const float *xp, *gp, *bp;
        if (k0 < 192)      { seg = 0; cbase = 0;   Csz = 192; xp = x1; gp = g1; bp = b1; }
        else if (k0 < 448) { seg = 1; cbase = 192; Csz = 256; xp = x2; gp = g2; bp = b2; }
        else               { seg = 2; cbase = 448; Csz = 512; xp = x3; gp = g3; bp = b3; }
        __syncthreads();
        // A tile: 128x32, LN'd, converted to bf16
        #pragma unroll
        for (int l = 0; l < 4; l++) {
            int fid = tid + l * 256;
            int row = fid >> 3, q4 = fid & 7;
            int token = token0 + row;
            int cl = k0 - cbase + q4 * 4;
            float4 xv = *reinterpret_cast<const float4*>(xp + (size_t)token * Csz + cl);
            float4 gv = *reinterpret_cast<const float4*>(gp + cl);
            float4 bv = *reinterpret_cast<const float4*>(bp + cl);
            float m = g_stats[(size_t)token * 6 + seg];
            float r = g_stats[(size_t)token * 6 + 3 + seg];
            float f0 = (xv.x - m) * (r * gv.x) + bv.x;
            float f1 = (xv.y - m) * (r * gv.y) + bv.y;
            float f2 = (xv.z - m) * (r * gv.z) + bv.z;
            float f3 = (xv.w - m) * (r * gv.w) + bv.w;
            __nv_bfloat162 p0 = __floats2bfloat162_rn(f0, f1);
            __nv_bfloat162 p1 = __floats2bfloat162_rn(f2, f3);
            uint2 u = make_uint2(*reinterpret_cast<uint32_t*>(&p0),
                                 *reinterpret_cast<uint32_t*>(&p1));
            *reinterpret_cast<uint2*>(&sm.s.A[row][q4 * 4]) = u;
        }
        // W tile: 96 x 32 bf16, [o][k] layout (col-major B for mma)
        for (int idx = tid; idx < 384; idx += 256) {
            int o = idx >> 2, kq = idx & 3;
            uint4 w = *reinterpret_cast<const uint4*>(g_wqkv + (size_t)o * 960 + k0 + kq * 8);
            *reinterpret_cast<uint4*>(&sm.s.W[o][kq * 8]) = w;
        }
        __syncthreads();
        #pragma unroll
        for (int ks = 0; ks < 32; ks += 16) {
            uint32_t afr[2][4], bfr[6][2];
            #pragma unroll
            for (int mr = 0; mr < 2; mr++) {
                int r0 = warpM * 32 + mr * 16;
                afr[mr][0] = *reinterpret_cast<const uint32_t*>(&sm.s.A[r0 + g    ][ks + tg * 2    ]);
                afr[mr][1] = *reinterpret_cast<const uint32_t*>(&sm.s.A[r0 + g + 8][ks + tg * 2    ]);
                afr[mr][2] = *reinterpret_cast<const uint32_t*>(&sm.s.A[r0 + g    ][ks + tg * 2 + 8]);
                afr[mr][3] = *reinterpret_cast<const uint32_t*>(&sm.s.A[r0 + g + 8][ks + tg * 2 + 8]);
            }
            #pragma unroll
            for (int nb = 0; nb < 6; nb++) {
                int o = warpN * 48 + nb * 8 + g;
                bfr[nb][0] = *reinterpret_cast<const uint32_t*>(&sm.s.W[o][ks + tg * 2    ]);
                bfr[nb][1] = *reinterpret_cast<const uint32_t*>(&sm.s.W[o][ks + tg * 2 + 8]);
            }
            #pragma unroll
            for (int mr = 0; mr < 2; mr++)
                #pragma unroll
                for (int nb = 0; nb < 6; nb++)
                    mma_bf16(acc[mr][nb], afr[mr], bfr[nb]);
        }
    }
    // Stage C to smem [o][tok] then coalesced uint4 stores (channel-major bf16)
    __syncthreads();
    #pragma unroll
    for (int mr = 0; mr < 2; mr++)
        #pragma unroll
        for (int nb = 0; nb < 6; nb++) {
            int oo = warpN * 48 + nb * 8 + tg * 2;
            int t0 = warpM * 32 + mr * 16 + g;
            sm.C[oo    ][t0    ] = __float2bfloat16(acc[mr][nb][0]);
            sm.C[oo + 1][t0    ] = __float2bfloat16(acc[mr][nb][1]);
            sm.C[oo    ][t0 + 8] = __float2bfloat16(acc[mr][nb][2]);
            sm.C[oo + 1][t0 + 8] = __float2bfloat16(acc[mr][nb][3]);
        }
    __syncthreads();
    const int bb = token0 >> 12;
    const int n0 = token0 & (NPIX - 1);
    #pragma unroll
    for (int i = 0; i < 6; i++) {
        int idx = tid + i * 256;          // 1536 uint4 total
        int o = idx >> 4, q = idx & 15;
        uint4 v = *reinterpret_cast<const uint4*>(&sm.C[o][q * 8]);
        *reinterpret_cast<uint4*>(g_multi + ((size_t)bb * 288 + o) * NPIX + n0 + q * 8) = v;
    }
}

// ---------------------------------------------------------------------------
// K3/K4: fused depthwise KxK + grouped 8x8 pointwise (bf16 in/out)
// ---------------------------------------------------------------------------
template<int K>
__global__ void __launch_bounds__(256) dwpw_kernel(const float* __restrict__ dw_w,
                                                   const float* __restrict__ pw_w,
                                                   int out_ch_base) {
    constexpr int R = K / 2;
    constexpr int T = 32 + 2 * R;
    __shared__ bf16  sin_[8][T][T];
    __shared__ float wdw[8][K * K];
    __shared__ float wpw[8][8];   // [in][out], broadcast-friendly
    const int b = blockIdx.z, g = blockIdx.y, tile = blockIdx.x;
    const int ty0 = (tile >> 1) * 32, tx0 = (tile & 1) * 32;
    const int tid = threadIdx.x;
    const bf16* src = g_multi + ((size_t)b * 288 + g * 8) * NPIX;

    for (int idx = tid; idx < 8 * T * T; idx += 256) {
        int ch = idx / (T * T); int rem = idx - ch * T * T;
        int yy = rem / T, xx = rem - yy * T;
        int gy = ty0 + yy - R, gx = tx0 + xx - R;
        bf16 v = __float2bfloat16(0.f);
        if (gy >= 0 && gy < HW && gx >= 0 && gx < HW) v = src[ch * NPIX + gy * HW + gx];
        sin_[ch][yy][xx] = v;
    }
    if (tid < 8 * K * K) {
        int ch = tid / (K * K); int kk = tid - ch * (K * K);
        wdw[ch][kk] = dw_w[(g * 8 + ch) * (K * K) + kk];
    }
    if (tid < 64) wpw[tid & 7][tid >> 3] = pw_w[(g * 8 + (tid >> 3)) * 8 + (tid & 7)];
    __syncthreads();

    bf16* dst = g_multi + ((size_t)b * 288 + out_ch_base + g * 8) * NPIX;
    #pragma unroll 1
    for (int pp = 0; pp < 4; pp++) {
        int p = tid + pp * 256;
        int py = p >> 5, px = p & 31;
        float o8[8];
        #pragma unroll
        for (int o = 0; o < 8; o++) o8[o] = 0.f;
        #pragma unroll 1
        for (int ch = 0; ch < 8; ch++) {
            float s = 0.f;
            #pragma unroll
            for (int ky = 0; ky < K; ky++)
                #pragma unroll
                for (int kx = 0; kx < K; kx++)
                    s = fmaf(__bfloat162float(sin_[ch][py + ky][px + kx]),
                             wdw[ch][ky * K + kx], s);
            #pragma unroll
            for (int o = 0; o < 8; o++) o8[o] = fmaf(wpw[ch][o], s, o8[o]);
        }
        int n = (ty0 + py) * HW + (tx0 + px);
        #pragma unroll
        for (int o = 0; o < 8; o++) dst[o * NPIX + n] = __float2bfloat16(o8[o]);
    }
}

// ---------------------------------------------------------------------------
// K5: linear attention per (b, g)  (bf16 in/out, fp32 math)
// ---------------------------------------------------------------------------
__global__ void __launch_bounds__(256) attn_kernel() {
    const int g = blockIdx.x, b = blockIdx.y;
    const int tid = threadIdx.x, lane = tid & 31, wrp = tid >> 5;
    const bf16* mg = g_multi + ((size_t)b * 288 + g * 24) * NPIX;

    float acc[9][8];
    #pragma unroll
    for (int d = 0; d < 9; d++)
        #pragma unroll
        for (int e = 0; e < 8; e++) acc[d][e] = 0.f;

    for (int n = tid; n < NPIX; n += 256) {
        float kv[8], vv[8];
        #pragma unroll
        for (int e = 0; e < 8; e++) kv[e] = fmaxf(__bfloat162float(mg[(8 + e) * NPIX + n]), 0.f);
        #pragma unroll
        for (int d = 0; d < 8; d++) vv[d] = __bfloat162float(mg[(16 + d) * NPIX + n]);
        #pragma unroll
        for (int d = 0; d < 8; d++)
            #pragma unroll
            for (int e = 0; e < 8; e++) acc[d][e] = fmaf(vv[d], kv[e], acc[d][e]);
        #pragma unroll
        for (int e = 0; e < 8; e++) acc[8][e] += kv[e];
    }
    __shared__ float red[8][72];
    __shared__ float vk[72];
    #pragma unroll
    for (int d = 0; d < 9; d++)
        #pragma unroll
        for (int e = 0; e < 8; e++) {
            float s = acc[d][e];
            #pragma unroll
            for (int off = 16; off > 0; off >>= 1) s += __shfl_xor_sync(0xffffffffu, s, off);
            if (lane == 0) red[wrp][d * 8 + e] = s;
        }
    __syncthreads();
    if (tid < 72) {
        float s = 0.f;
        #pragma unroll
        for (int w = 0; w < 8; w++) s += red[w][tid];
        vk[tid] = s;
    }
    __syncthreads();

    bf16* ab = g_att + ((size_t)b * C3 + g * 8) * NPIX;
    for (int n = tid; n < NPIX; n += 256) {
        float num[8];
        #pragma unroll
        for (int d = 0; d < 8; d++) num[d] = 0.f;
        float den = 1e-15f;
        #pragma unroll
        for (int e = 0; e < 8; e++) {
            float q = fmaxf(__bfloat162float(mg[e * NPIX + n]), 0.f);
            #pragma unroll
            for (int d = 0; d < 8; d++) num[d] = fmaf(vk[d * 8 + e], q, num[d]);
            den = fmaf(vk[64 + e], q, den);
        }
        float inv = 1.f / den;
        #pragma unroll
        for (int d = 0; d < 8; d++) ab[d * NPIX + n] = __float2bfloat16(num[d] * inv);
    }
}

// ---------------------------------------------------------------------------
// K6: proj GEMM (M=131072, N=960, K=96) bf16 tensor cores
//     + BN + residual + 3-way split, staged fully-coalesced float4 stores.
// Grid: (10 o-chunks [fast], 1024 token tiles) so o-chunks share A in L2.
// ---------------------------------------------------------------------------
__global__ void __launch_bounds__(256) proj_gemm_kernel(
    const float* __restrict__ bn_g, const float* __restrict__ bn_b,
    const float* __restrict__ bn_m, const float* __restrict__ bn_v,
    const float* __restrict__ x1, const float* __restrict__ x2, const float* __restrict__ x3,
    float* __restrict__ out) {
    __shared__ union {
        struct { bf16 A[128][40]; bf16 W[96][104]; } s;  // 30208 B
        bf16 C[128][104];                                 // 26624 B
    } sm;
    __shared__ float scv[96], shv[96];
    const int tid  = threadIdx.x;
    const int warp = tid >> 5, lane = tid & 31;
    const int warpM = warp & 3, warpN = warp >> 2;
    const int g = lane >> 2, tg = lane & 3;
    const int o0 = blockIdx.x * 96;
    const int token0 = blockIdx.y * 128;
    const int bb = token0 >> 12;
    const int n0 = token0 & (NPIX - 1);

    if (tid < 96) {
        int o = o0 + tid;
        float sc = bn_g[o] * rsqrtf(bn_v[o] + 1e-5f);
        scv[tid] = sc;
        shv[tid] = bn_b[o] - bn_m[o] * sc;
    }
    // W: 96 rows x 96 k, loaded once
    for (int idx = tid; idx < 96 * 12; idx += 256) {
        int o = idx / 12, kq = idx % 12;
        uint4 w = *reinterpret_cast<const uint4*>(g_wproj + (size_t)(o0 + o) * 96 + kq * 8);
        *reinterpret_cast<uint4*>(&sm.s.W[o][kq * 8]) = w;
    }

    float acc[2][6][4];
    #pragma unroll
    for (int mr = 0; mr < 2; mr++)
        #pragma unroll
        for (int nb = 0; nb < 6; nb++)
            #pragma unroll
            for (int q = 0; q < 4; q++) acc[mr][nb][q] = 0.f;

    for (int kt = 0; kt < 3; kt++) {
        const int k0 = kt * 32;
        __syncthreads();
        // A: transpose-load 32 ch x 128 tok from channel-major g_att
        const bf16* attb = g_att + ((size_t)bb * C3 + k0) * NPIX + n0;
        #pragma unroll
        for (int l = 0; l < 4; l++) {
            int idx = tid + l * 256;           // 1024 quads
            int ch = idx >> 5, tq = idx & 31;
            uint2 v = *reinterpret_cast<const uint2*>(attb + (size_t)ch * NPIX + tq * 4);
            const bf16* hv = reinterpret_cast<const bf16*>(&v);
            sm.s.A[tq * 4 + 0][ch] = hv[0];
            sm.s.A[tq * 4 + 1][ch] = hv[1];
            sm.s.A[tq * 4 + 2][ch] = hv[2];
            sm.s.A[tq * 4 + 3][ch] = hv[3];
        }
        __syncthreads();
        #pragma unroll
        for (int ks = 0; ks < 32; ks += 16) {
            uint32_t afr[2][4], bfr[6][2];
            #pragma unroll
            for (int mr = 0; mr < 2; mr++) {
                int r0 = warpM * 32 + mr * 16;
                afr[mr][0] = *reinterpret_cast<const uint32_t*>(&sm.s.A[r0 + g    ][ks + tg * 2    ]);
                afr[mr][1] = *reinterpret_cast<const uint32_t*>(&sm.s.A[r0 + g + 8][ks + tg * 2    ]);
                afr[mr][2] = *reinterpret_cast<const uint32_t*>(&sm.s.A[r0 + g    ][ks + tg * 2 + 8]);
                afr[mr][3] = *reinterpret_cast<const uint32_t*>(&sm.s.A[r0 + g + 8][ks + tg * 2 + 8]);
            }
            #pragma unroll
            for (int nb = 0; nb < 6; nb++) {
                int o = warpN * 48 + nb * 8 + g;
                bfr[nb][0] = *reinterpret_cast<const uint32_t*>(&sm.s.W[o][k0 + ks + tg * 2    ]);
                bfr[nb][1] = *reinterpret_cast<const uint32_t*>(&sm.s.W[o][k0 + ks + tg * 2 + 8]);
            }
            #pragma unroll
            for (int mr = 0; mr < 2; mr++)
                #pragma unroll
                for (int nb = 0; nb < 6; nb++)
                    mma_bf16(acc[mr][nb], afr[mr], bfr[nb]);
        }
    }
    // Stage C [tok][o] (bf16) then coalesced BN+residual float4 stores
    __syncthreads();
    #pragma unroll
    for (int mr = 0; mr < 2; mr++)
        #pragma unroll
        for (int nb = 0; nb < 6; nb++) {
            int oo = warpN * 48 + nb * 8 + tg * 2;
            int t0 = warpM * 32 + mr * 16 + g;
            __nv_bfloat162 p0 = __floats2bfloat162_rn(acc[mr][nb][0], acc[mr][nb][1]);
            __nv_bfloat162 p1 = __floats2bfloat162_rn(acc[mr][nb][2], acc[mr][nb][3]);
            *reinterpret_cast<uint32_t*>(&sm.C[t0    ][oo]) = *reinterpret_cast<uint32_t*>(&p0);
            *reinterpret_cast<uint32_t*>(&sm.C[t0 + 8][oo]) = *reinterpret_cast<uint32_t*>(&p1);
        }
    __syncthreads();
    #pragma unroll
    for (int i = 0; i < 12; i++) {
        int idx = tid + i * 256;            // 3072 quads = 128 tok x 24
        int tl = idx / 24, qo = idx % 24;
        int o_g = o0 + qo * 4;
        int token = token0 + tl;
        const float* xr; size_t obase; int Csz, cl;
        if (o_g < 192)      { xr = x1; obase = 0;                  Csz = 192; cl = o_g; }
        else if (o_g < 448) { xr = x2; obase = (size_t)NTOK * 192; Csz = 256; cl = o_g - 192; }
        else                { xr = x3; obase = (size_t)NTOK * 448; Csz = 512; cl = o_g - 448; }
        size_t base = (size_t)token * Csz + cl;
        float4 xv = *reinterpret_cast<const float4*>(xr + base);
        uint2 cu = *reinterpret_cast<const uint2*>(&sm.C[tl][qo * 4]);
        const bf16* ch4 = reinterpret_cast<const bf16*>(&cu);
        int ol = qo * 4;
        float4 ov;
        ov.x = scv[ol    ] * __bfloat162float(ch4[0]) + shv[ol    ] + xv.x;
        ov.y = scv[ol + 1] * __bfloat162float(ch4[1]) + shv[ol + 1] + xv.y;
        ov.z = scv[ol + 2] * __bfloat162float(ch4[2]) + shv[ol + 2] + xv.z;
        ov.w = scv[ol + 3] * __bfloat162float(ch4[3]) + shv[ol + 3] + xv.w;
        *reinterpret_cast<float4*>(out + obase + base) = ov;
    }
}

// ---------------------------------------------------------------------------
// Launch
// ---------------------------------------------------------------------------
extern "C" void kernel_launch(void* const* d_in, const int* in_sizes, int n_in,
                              void* d_out, int out_size) {
    (void)out_size;
    const float *x1 = 0, *x2 = 0, *x3 = 0;
    const float *g1 = 0, *b1 = 0, *g2 = 0, *b2 = 0, *g3 = 0, *b3 = 0;
    const float *qkv_w = 0, *dw3 = 0, *pw3 = 0, *dw5 = 0, *pw5 = 0, *proj_w = 0;
    const float *bn_g = 0, *bn_b = 0, *bn_m = 0, *bn_v = 0;
    int c192 = 0, c256 = 0, c512 = 0, cW = 0, c768 = 0, c960 = 0;
    for (int i = 0; i < n_in; i++) {
        const float* p = (const float*)d_in[i];
        switch (in_sizes[i]) {
            case 25165824: x1 = p; break;
            case 33554432: x2 = p; break;
            case 67108864: x3 = p; break;
            case 192: (c192++ ? b1 : g1) = p; break;
            case 256: (c256++ ? b2 : g2) = p; break;
            case 512: (c512++ ? b3 : g3) = p; break;
            case 92160: (cW++ ? proj_w : qkv_w) = p; break;
            case 864:  dw3 = p; break;
            case 2400: dw5 = p; break;
            case 768: (c768++ ? pw5 : pw3) = p; break;
            case 960: {
                if      (c960 == 0) bn_g = p;
                else if (c960 == 1) bn_b = p;
                else if (c960 == 2) bn_m = p;
                else                bn_v = p;
                c960++;
            } break;
            default: break;
        }
    }
    float* out = (float*)d_out;

    prep_weights<<<(C3 * CIN + 255) / 256, 256>>>(qkv_w, proj_w);
    ln_stats_kernel<<<NTOK / 8, 256>>>(x1, x2, x3);
    qkv_gemm_kernel<<<NTOK / 128, 256>>>(x1, x2, x3, g1, b1, g2, b2, g3, b3);
    dwpw_kernel<3><<<dim3(4, NG, NB), 256>>>(dw3, pw3, 96);
    dwpw_kernel<5><<<dim3(4, NG, NB), 256>>>(dw5, pw5, 192);
    attn_kernel<<<dim3(NG, NB), 256>>>();
    proj_gemm_kernel<<<dim3(10, NTOK / 128), 256>>>(bn_g, bn_b, bn_m, bn_v,
                                                    x1, x2, x3, out);
}

// round 4
// speedup vs baseline: 2.3127x; 1.1291x over previous
#include <cuda_runtime.h>
#include <cuda_bf16.h>
#include <cstdint>
#include <cstddef>

// ---------------------------------------------------------------------------
#define NB    32
#define NPIX  4096
#define NTOK  (NB*NPIX)   // 131072
#define CIN   960
#define C3    96
#define NG    12
#define HW    64

typedef __nv_bfloat16 bf16;

// ---------------------------------------------------------------------------
// Scratch (device globals)
// ---------------------------------------------------------------------------
__device__ bf16  g_multi[(size_t)NB * 288 * NPIX];     // [b][ch][n] bf16 (75 MB)
__device__ bf16  g_att  [(size_t)NB * C3  * NPIX];     // [b][ch][n] bf16 (25 MB)
__device__ bf16  g_wqkv [C3 * CIN];
__device__ bf16  g_wproj[CIN * C3];

// ---------------------------------------------------------------------------
// K0: weight conversion fp32 -> bf16
// ---------------------------------------------------------------------------
__global__ void prep_weights(const float* __restrict__ qkv_w,
                             const float* __restrict__ proj_w) {
    int i = blockIdx.x * 256 + threadIdx.x;
    if (i < C3 * CIN) {
        g_wqkv[i]  = __float2bfloat16(qkv_w[i]);
        g_wproj[i] = __float2bfloat16(proj_w[i]);
    }
}

// ---------------------------------------------------------------------------
// mma.sync m16n8k16 bf16 helper
// ---------------------------------------------------------------------------
__device__ __forceinline__ void mma_bf16(float* c, const uint32_t* a, const uint32_t* b) {
    asm volatile(
        "mma.sync.aligned.m16n8k16.row.col.f32.bf16.bf16.f32 "
        "{%0,%1,%2,%3}, {%4,%5,%6,%7}, {%8,%9}, {%0,%1,%2,%3};\n"
        : "+f"(c[0]), "+f"(c[1]), "+f"(c[2]), "+f"(c[3])
        : "r"(a[0]), "r"(a[1]), "r"(a[2]), "r"(a[3]), "r"(b[0]), "r"(b[1]));
}

// ---------------------------------------------------------------------------
// K1: qkv GEMM (M=131072, N=96, K=960) with FUSED LayerNorm (stats + apply).
// Pass 1: warp-per-token streaming stats over the block's 128x960 fp32 tile.
// Pass 2: K-loop re-reads the tile (L2-hot) with LN applied, bf16 mma.
// ---------------------------------------------------------------------------
__global__ void __launch_bounds__(256) qkv_gemm_kernel(
    const float* __restrict__ x1, const float* __restrict__ x2, const float* __restrict__ x3,
    const float* __restrict__ g1, const float* __restrict__ b1,
    const float* __restrict__ g2, const float* __restrict__ b2,
    const float* __restrict__ g3, const float* __restrict__ b3) {
    __shared__ union {
        struct { bf16 A[128][40]; bf16 W[96][40]; } s;   // 17920 B
        bf16 C[96][136];                                  // 26112 B
    } sm;
    __shared__ float st[128][6];   // mean[3], rstd[3] per token
    const int tid  = threadIdx.x;
    const int warp = tid >> 5, lane = tid & 31;
    const int warpM = warp & 3, warpN = warp >> 2;
    const int g = lane >> 2, tg = lane & 3;
    const int token0 = blockIdx.x * 128;

    // ---- Pass 1: LN stats (streams the tile from DRAM; warms L2) ----
    {
        const float* xs[3] = {x1, x2, x3};
        const int    Cs[3] = {192, 256, 512};
        for (int t = warp; t < 128; t += 8) {
            int token = token0 + t;
            #pragma unroll
            for (int s = 0; s < 3; s++) {
                const float* p = xs[s] + (size_t)token * Cs[s];
                float sum = 0.f, sq = 0.f;
                for (int c = lane; c < Cs[s]; c += 32) { float v = p[c]; sum += v; sq += v * v; }
                #pragma unroll
                for (int off = 16; off > 0; off >>= 1) {
                    sum += __shfl_xor_sync(0xffffffffu, sum, off);
                    sq  += __shfl_xor_sync(0xffffffffu, sq,  off);
                }
                if (lane == 0) {
                    float m   = sum / (float)Cs[s];
                    float var = sq / (float)Cs[s] - m * m;
                    st[t][s]     = m;
                    st[t][3 + s] = rsqrtf(var + 1e-6f);
                }
            }
        }
    }
    __syncthreads();

    float acc[2][6][4];
    #pragma unroll
    for (int mr = 0; mr < 2; mr++)
        #pragma unroll
        for (int nb = 0; nb < 6; nb++)
            #pragma unroll
            for (int q = 0; q < 4; q++) acc[mr][nb][q] = 0.f;

    for (int kt = 0; kt < 30; kt++) {
        const int k0 = kt * 32;
        int seg, cbase, Csz; const float *xp, *gp, *bp;
        if (k0 < 192)      { seg = 0; cbase = 0;   Csz = 192; xp = x1; gp = g1; bp = b1; }
        else if (k0 < 448) { seg = 1; cbase = 192; Csz = 256; xp = x2; gp = g2; bp = b2; }
        else               { seg = 2; cbase = 448; Csz = 512; xp = x3; gp = g3; bp = b3; }
        __syncthreads();
        // A tile: 128x32, LN'd, bf16
        #pragma unroll
        for (int l = 0; l < 4; l++) {
            int fid = tid + l * 256;
            int row = fid >> 3, q4 = fid & 7;
            int token = token0 + row;
            int cl = k0 - cbase + q4 * 4;
            float4 xv = *reinterpret_cast<const float4*>(xp + (size_t)token * Csz + cl);
            float4 gv = *reinterpret_cast<const float4*>(gp + cl);
            float4 bv = *reinterpret_cast<const float4*>(bp + cl);
            float m = st[row][seg];
            float r = st[row][3 + seg];
            float f0 = (xv.x - m) * (r * gv.x) + bv.x;
            float f1 = (xv.y - m) * (r * gv.y) + bv.y;
            float f2 = (xv.z - m) * (r * gv.z) + bv.z;
            float f3 = (xv.w - m) * (r * gv.w) + bv.w;
            __nv_bfloat162 p0 = __floats2bfloat162_rn(f0, f1);
            __nv_bfloat162 p1 = __floats2bfloat162_rn(f2, f3);
            uint2 u = make_uint2(*reinterpret_cast<uint32_t*>(&p0),
                                 *reinterpret_cast<uint32_t*>(&p1));
            *reinterpret_cast<uint2*>(&sm.s.A[row][q4 * 4]) = u;
        }
        // W tile
        for (int idx = tid; idx < 384; idx += 256) {
            int o = idx >> 2, kq = idx & 3;
            uint4 w = *reinterpret_cast<const uint4*>(g_wqkv + (size_t)o * 960 + k0 + kq * 8);
            *reinterpret_cast<uint4*>(&sm.s.W[o][kq * 8]) = w;
        }
        __syncthreads();
        #pragma unroll
        for (int ks = 0; ks < 32; ks += 16) {
            uint32_t afr[2][4], bfr[6][2];
            #pragma unroll
            for (int mr = 0; mr < 2; mr++) {
                int r0 = warpM * 32 + mr * 16;
                afr[mr][0] = *reinterpret_cast<const uint32_t*>(&sm.s.A[r0 + g    ][ks + tg * 2    ]);
                afr[mr][1] = *reinterpret_cast<const uint32_t*>(&sm.s.A[r0 + g + 8][ks + tg * 2    ]);
                afr[mr][2] = *reinterpret_cast<const uint32_t*>(&sm.s.A[r0 + g    ][ks + tg * 2 + 8]);
                afr[mr][3] = *reinterpret_cast<const uint32_t*>(&sm.s.A[r0 + g + 8][ks + tg * 2 + 8]);
            }
            #pragma unroll
            for (int nb = 0; nb < 6; nb++) {
                int o = warpN * 48 + nb * 8 + g;
                bfr[nb][0] = *reinterpret_cast<const uint32_t*>(&sm.s.W[o][ks + tg * 2    ]);
                bfr[nb][1] = *reinterpret_cast<const uint32_t*>(&sm.s.W[o][ks + tg * 2 + 8]);
            }
            #pragma unroll
            for (int mr = 0; mr < 2; mr++)
                #pragma unroll
                for (int nb = 0; nb < 6; nb++)
                    mma_bf16(acc[mr][nb], afr[mr], bfr[nb]);
        }
    }
    // Stage C to smem [o][tok] then coalesced uint4 stores (channel-major bf16)
    __syncthreads();
    #pragma unroll
    for (int mr = 0; mr < 2; mr++)
        #pragma unroll
        for (int nb = 0; nb < 6; nb++) {
            int oo = warpN * 48 + nb * 8 + tg * 2;
            int t0 = warpM * 32 + mr * 16 + g;
            sm.C[oo    ][t0    ] = __float2bfloat16(acc[mr][nb][0]);
            sm.C[oo + 1][t0    ] = __float2bfloat16(acc[mr][nb][1]);
            sm.C[oo    ][t0 + 8] = __float2bfloat16(acc[mr][nb][2]);
            sm.C[oo + 1][t0 + 8] = __float2bfloat16(acc[mr][nb][3]);
        }
    __syncthreads();
    const int bb = token0 >> 12;
    const int n0 = token0 & (NPIX - 1);
    #pragma unroll
    for (int i = 0; i < 6; i++) {
        int idx = tid + i * 256;
        int o = idx >> 4, q = idx & 15;
        uint4 v = *reinterpret_cast<const uint4*>(&sm.C[o][q * 8]);
        *reinterpret_cast<uint4*>(g_multi + ((size_t)bb * 288 + o) * NPIX + n0 + q * 8) = v;
    }
}

// ---------------------------------------------------------------------------
// K2: MERGED dw3x3+pw AND dw5x5+pw. One input tile load serves both paths.
// fp32 smem tile; 5x5 register window, inner 3x3 reused for the small conv.
// ---------------------------------------------------------------------------
__global__ void __launch_bounds__(256) dwpw_merged_kernel(
        const float* __restrict__ dw3_w, const float* __restrict__ pw3_w,
        const float* __restrict__ dw5_w, const float* __restrict__ pw5_w) {
    constexpr int T = 36;    // 32 + 2*2
    __shared__ float sin_[8][T][T];      // 41472 B
    __shared__ float wd3[8][9], wd5[8][25];
    __shared__ float wp3[8][8], wp5[8][8];   // [in][out]
    const int b = blockIdx.z, g = blockIdx.y, tile = blockIdx.x;
    const int ty0 = (tile >> 1) * 32, tx0 = (tile & 1) * 32;
    const int tid = threadIdx.x;
    const bf16* src = g_multi + ((size_t)b * 288 + g * 8) * NPIX;

    for (int idx = tid; idx < 8 * T * T; idx += 256) {
        int ch = idx / (T * T); int rem = idx - ch * T * T;
        int yy = rem / T, xx = rem - yy * T;
        int gy = ty0 + yy - 2, gx = tx0 + xx - 2;
        float v = 0.f;
        if (gy >= 0 && gy < HW && gx >= 0 && gx < HW)
            v = __bfloat162float(src[ch * NPIX + gy * HW + gx]);
        sin_[ch][yy][xx] = v;
    }
    if (tid < 72)  { int ch = tid / 9,  kk = tid % 9;  wd3[ch][kk] = dw3_w[(g * 8 + ch) * 9  + kk]; }
    else if (tid < 136) { int t = tid - 72; wp3[t & 7][t >> 3] = pw3_w[(g * 8 + (t >> 3)) * 8 + (t & 7)]; }
    else if (tid < 200) { int t = tid - 136; wp5[t & 7][t >> 3] = pw5_w[(g * 8 + (t >> 3)) * 8 + (t & 7)]; }
    for (int t = tid; t < 200; t += 256) {
        int ch = t / 25, kk = t % 25;
        wd5[ch][kk] = dw5_w[(g * 8 + ch) * 25 + kk];
    }
    __syncthreads();

    bf16* dst3 = g_multi + ((size_t)b * 288 +  96 + g * 8) * NPIX;
    bf16* dst5 = g_multi + ((size_t)b * 288 + 192 + g * 8) * NPIX;
    #pragma unroll 1
    for (int pp = 0; pp < 4; pp++) {
        int p = tid + pp * 256;
        int py = p >> 5, px = p & 31;
        float o3[8], o5[8];
        #pragma unroll
        for (int o = 0; o < 8; o++) { o3[o] = 0.f; o5[o] = 0.f; }
        #pragma unroll 1
        for (int ch = 0; ch < 8; ch++) {
            float w[5][5];
            #pragma unroll
            for (int ky = 0; ky < 5; ky++)
                #pragma unroll
                for (int kx = 0; kx < 5; kx++)
                    w[ky][kx] = sin_[ch][py + ky][px + kx];
            float s5 = 0.f;
            #pragma unroll
            for (int ky = 0; ky < 5; ky++)
                #pragma unroll
                for (int kx = 0; kx < 5; kx++)
                    s5 = fmaf(w[ky][kx], wd5[ch][ky * 5 + kx], s5);
            float s3 = 0.f;
            #pragma unroll
            for (int ky = 0; ky < 3; ky++)
                #pragma unroll
                for (int kx = 0; kx < 3; kx++)
                    s3 = fmaf(w[ky + 1][kx + 1], wd3[ch][ky * 3 + kx], s3);
            #pragma unroll
            for (int o = 0; o < 8; o++) {
                o3[o] = fmaf(wp3[ch][o], s3, o3[o]);
                o5[o] = fmaf(wp5[ch][o], s5, o5[o]);
            }
        }
        int n = (ty0 + py) * HW + (tx0 + px);
        #pragma unroll
        for (int o = 0; o < 8; o++) {
            dst3[o * NPIX + n] = __float2bfloat16(o3[o]);
            dst5[o * NPIX + n] = __float2bfloat16(o5[o]);
        }
    }
}

// ---------------------------------------------------------------------------
// K3: linear attention per (b, g), 2 pixels/thread with bf16x2 I/O
// ---------------------------------------------------------------------------
__global__ void __launch_bounds__(256) attn_kernel() {
    const int g = blockIdx.x, b = blockIdx.y;
    const int tid = threadIdx.x, lane = tid & 31, wrp = tid >> 5;
    const bf16* mg = g_multi + ((size_t)b * 288 + g * 24) * NPIX;

    float acc[9][8];
    #pragma unroll
    for (int d = 0; d < 9; d++)
        #pragma unroll
        for (int e = 0; e < 8; e++) acc[d][e] = 0.f;

    for (int n = tid * 2; n < NPIX; n += 512) {
        float k0[8], k1[8], v0[8], v1[8];
        #pragma unroll
        for (int e = 0; e < 8; e++) {
            __nv_bfloat162 kp = *reinterpret_cast<const __nv_bfloat162*>(mg + (8 + e) * NPIX + n);
            k0[e] = fmaxf(__bfloat162float(kp.x), 0.f);
            k1[e] = fmaxf(__bfloat162float(kp.y), 0.f);
        }
        #pragma unroll
        for (int d = 0; d < 8; d++) {
            __nv_bfloat162 vp = *reinterpret_cast<const __nv_bfloat162*>(mg + (16 + d) * NPIX + n);
            v0[d] = __bfloat162float(vp.x);
            v1[d] = __bfloat162float(vp.y);
        }
        #pragma unroll
        for (int d = 0; d < 8; d++)
            #pragma unroll
            for (int e = 0; e < 8; e++)
                acc[d][e] = fmaf(v1[d], k1[e], fmaf(v0[d], k0[e], acc[d][e]));
        #pragma unroll
        for (int e = 0; e < 8; e++) acc[8][e] += k0[e] + k1[e];
    }
    __shared__ float red[8][72];
    __shared__ float vk[72];
    #pragma unroll
    for (int d = 0; d < 9; d++)
        #pragma unroll
        for (int e = 0; e < 8; e++) {
            float s = acc[d][e];
            #pragma unroll
            for (int off = 16; off > 0; off >>= 1) s += __shfl_xor_sync(0xffffffffu, s, off);
            if (lane == 0) red[wrp][d * 8 + e] = s;
        }
    __syncthreads();
    if (tid < 72) {
        float s = 0.f;
        #pragma unroll
        for (int w = 0; w < 8; w++) s += red[w][tid];
        vk[tid] = s;
    }
    __syncthreads();

    bf16* ab = g_att + ((size_t)b * C3 + g * 8) * NPIX;
    for (int n = tid * 2; n < NPIX; n += 512) {
        float n0[8], n1[8];
        #pragma unroll
        for (int d = 0; d < 8; d++) { n0[d] = 0.f; n1[d] = 0.f; }
        float d0 = 1e-15f, d1 = 1e-15f;
        #pragma unroll
        for (int e = 0; e < 8; e++) {
            __nv_bfloat162 qp = *reinterpret_cast<const __nv_bfloat162*>(mg + e * NPIX + n);
            float q0 = fmaxf(__bfloat162float(qp.x), 0.f);
            float q1 = fmaxf(__bfloat162float(qp.y), 0.f);
            #pragma unroll
            for (int d = 0; d < 8; d++) {
                n0[d] = fmaf(vk[d * 8 + e], q0, n0[d]);
                n1[d] = fmaf(vk[d * 8 + e], q1, n1[d]);
            }
            d0 = fmaf(vk[64 + e], q0, d0);
            d1 = fmaf(vk[64 + e], q1, d1);
        }
        float i0 = 1.f / d0, i1 = 1.f / d1;
        #pragma unroll
        for (int d = 0; d < 8; d++) {
            __nv_bfloat162 ov = __floats2bfloat162_rn(n0[d] * i0, n1[d] * i1);
            *reinterpret_cast<__nv_bfloat162*>(ab + d * NPIX + n) = ov;
        }
    }
}

// ---------------------------------------------------------------------------
// K4: proj GEMM (M=131072, N=960, K=96) bf16 mma + BN + residual + split
// ---------------------------------------------------------------------------
__global__ void __launch_bounds__(256) proj_gemm_kernel(
    const float* __restrict__ bn_g, const float* __restrict__ bn_b,
    const float* __restrict__ bn_m, const float* __restrict__ bn_v,
    const float* __restrict__ x1, const float* __restrict__ x2, const float* __restrict__ x3,
    float* __restrict__ out) {
    __shared__ union {
        struct { bf16 A[128][40]; bf16 W[96][104]; } s;
        bf16 C[128][104];
    } sm;
    __shared__ float scv[96], shv[96];
    const int tid  = threadIdx.x;
    const int warp = tid >> 5, lane = tid & 31;
    const int warpM = warp & 3, warpN = warp >> 2;
    const int g = lane >> 2, tg = lane & 3;
    const int o0 = blockIdx.x * 96;
    const int token0 = blockIdx.y * 128;
    const int bb = token0 >> 12;
    const int n0 = token0 & (NPIX - 1);

    if (tid < 96) {
        int o = o0 + tid;
        float sc = bn_g[o] * rsqrtf(bn_v[o] + 1e-5f);
        scv[tid] = sc;
        shv[tid] = bn_b[o] - bn_m[o] * sc;
    }
    for (int idx = tid; idx < 96 * 12; idx += 256) {
        int o = idx / 12, kq = idx % 12;
        uint4 w = *reinterpret_cast<const uint4*>(g_wproj + (size_t)(o0 + o) * 96 + kq * 8);
        *reinterpret_cast<uint4*>(&sm.s.W[o][kq * 8]) = w;
    }

    float acc[2][6][4];
    #pragma unroll
    for (int mr = 0; mr < 2; mr++)
        #pragma unroll
        for (int nb = 0; nb < 6; nb++)
            #pragma unroll
            for (int q = 0; q < 4; q++) acc[mr][nb][q] = 0.f;

    for (int kt = 0; kt < 3; kt++) {
        const int k0 = kt * 32;
        __syncthreads();
        const bf16* attb = g_att + ((size_t)bb * C3 + k0) * NPIX + n0;
        #pragma unroll
        for (int l = 0; l < 4; l++) {
            int idx = tid + l * 256;
            int ch = idx >> 5, tq = idx & 31;
            uint2 v = *reinterpret_cast<const uint2*>(attb + (size_t)ch * NPIX + tq * 4);
            const bf16* hv = reinterpret_cast<const bf16*>(&v);
            sm.s.A[tq * 4 + 0][ch] = hv[0];
            sm.s.A[tq * 4 + 1][ch] = hv[1];
            sm.s.A[tq * 4 + 2][ch] = hv[2];
            sm.s.A[tq * 4 + 3][ch] = hv[3];
        }
        __syncthreads();
        #pragma unroll
        for (int ks = 0; ks < 32; ks += 16) {
            uint32_t afr[2][4], bfr[6][2];
            #pragma unroll
            for (int mr = 0; mr < 2; mr++) {
                int r0 = warpM * 32 + mr * 16;
                afr[mr][0] = *reinterpret_cast<const uint32_t*>(&sm.s.A[r0 + g    ][ks + tg * 2    ]);
                afr[mr][1] = *reinterpret_cast<const uint32_t*>(&sm.s.A[r0 + g + 8][ks + tg * 2    ]);
                afr[mr][2] = *reinterpret_cast<const uint32_t*>(&sm.s.A[r0 + g    ][ks + tg * 2 + 8]);
                afr[mr][3] = *reinterpret_cast<const uint32_t*>(&sm.s.A[r0 + g + 8][ks + tg * 2 + 8]);
            }
            #pragma unroll
            for (int nb = 0; nb < 6; nb++) {
                int o = warpN * 48 + nb * 8 + g;
                bfr[nb][0] = *reinterpret_cast<const uint32_t*>(&sm.s.W[o][k0 + ks + tg * 2    ]);
                bfr[nb][1] = *reinterpret_cast<const uint32_t*>(&sm.s.W[o][k0 + ks + tg * 2 + 8]);
            }
            #pragma unroll
            for (int mr = 0; mr < 2; mr++)
                #pragma unroll
                for (int nb = 0; nb < 6; nb++)
                    mma_bf16(acc[mr][nb], afr[mr], bfr[nb]);
        }
    }
    __syncthreads();
    #pragma unroll
    for (int mr = 0; mr < 2; mr++)
        #pragma unroll
        for (int nb = 0; nb < 6; nb++) {
            int oo = warpN * 48 + nb * 8 + tg * 2;
            int t0 = warpM * 32 + mr * 16 + g;
            __nv_bfloat162 p0 = __floats2bfloat162_rn(acc[mr][nb][0], acc[mr][nb][1]);
            __nv_bfloat162 p1 = __floats2bfloat162_rn(acc[mr][nb][2], acc[mr][nb][3]);
            *reinterpret_cast<uint32_t*>(&sm.C[t0    ][oo]) = *reinterpret_cast<uint32_t*>(&p0);
            *reinterpret_cast<uint32_t*>(&sm.C[t0 + 8][oo]) = *reinterpret_cast<uint32_t*>(&p1);
        }
    __syncthreads();
    #pragma unroll
    for (int i = 0; i < 12; i++) {
        int idx = tid + i * 256;
        int tl = idx / 24, qo = idx % 24;
        int o_g = o0 + qo * 4;
        int token = token0 + tl;
        const float* xr; size_t obase; int Csz, cl;
        if (o_g < 192)      { xr = x1; obase = 0;                  Csz = 192; cl = o_g; }
        else if (o_g < 448) { xr = x2; obase = (size_t)NTOK * 192; Csz = 256; cl = o_g - 192; }
        else                { xr = x3; obase = (size_t)NTOK * 448; Csz = 512; cl = o_g - 448; }
        size_t base = (size_t)token * Csz + cl;
        float4 xv = *reinterpret_cast<const float4*>(xr + base);
        uint2 cu = *reinterpret_cast<const uint2*>(&sm.C[tl][qo * 4]);
        const bf16* ch4 = reinterpret_cast<const bf16*>(&cu);
        int ol = qo * 4;
        float4 ov;
        ov.x = scv[ol    ] * __bfloat162float(ch4[0]) + shv[ol    ] + xv.x;
        ov.y = scv[ol + 1] * __bfloat162float(ch4[1]) + shv[ol + 1] + xv.y;
        ov.z = scv[ol + 2] * __bfloat162float(ch4[2]) + shv[ol + 2] + xv.z;
        ov.w = scv[ol + 3] * __bfloat162float(ch4[3]) + shv[ol + 3] + xv.w;
        *reinterpret_cast<float4*>(out + obase + base) = ov;
    }
}

// ---------------------------------------------------------------------------
// Launch
// ---------------------------------------------------------------------------
extern "C" void kernel_launch(void* const* d_in, const int* in_sizes, int n_in,
                              void* d_out, int out_size) {
    (void)out_size;
    const float *x1 = 0, *x2 = 0, *x3 = 0;
    const float *g1 = 0, *b1 = 0, *g2 = 0, *b2 = 0, *g3 = 0, *b3 = 0;
    const float *qkv_w = 0, *dw3 = 0, *pw3 = 0, *dw5 = 0, *pw5 = 0, *proj_w = 0;
    const float *bn_g = 0, *bn_b = 0, *bn_m = 0, *bn_v = 0;
    int c192 = 0, c256 = 0, c512 = 0, cW = 0, c768 = 0, c960 = 0;
    for (int i = 0; i < n_in; i++) {
        const float* p = (const float*)d_in[i];
        switch (in_sizes[i]) {
            case 25165824: x1 = p; break;
            case 33554432: x2 = p; break;
            case 67108864: x3 = p; break;
            case 192: (c192++ ? b1 : g1) = p; break;
            case 256: (c256++ ? b2 : g2) = p; break;
            case 512: (c512++ ? b3 : g3) = p; break;
            case 92160: (cW++ ? proj_w : qkv_w) = p; break;
            case 864:  dw3 = p; break;
            case 2400: dw5 = p; break;
            case 768: (c768++ ? pw5 : pw3) = p; break;
            case 960: {
                if      (c960 == 0) bn_g = p;
                else if (c960 == 1) bn_b = p;
                else if (c960 == 2) bn_m = p;
                else                bn_v = p;
                c960++;
            } break;
            default: break;
        }
    }
    float* out = (float*)d_out;

    prep_weights<<<(C3 * CIN + 255) / 256, 256>>>(qkv_w, proj_w);
    qkv_gemm_kernel<<<NTOK / 128, 256>>>(x1, x2, x3, g1, b1, g2, b2, g3, b3);
    dwpw_merged_kernel<<<dim3(4, NG, NB), 256>>>(dw3, pw3, dw5, pw5);
    attn_kernel<<<dim3(NG, NB), 256>>>();
    proj_gemm_kernel<<<dim3(10, NTOK / 128), 256>>>(bn_g, bn_b, bn_m, bn_v,
                                                    x1, x2, x3, out);
}

// round 5
// speedup vs baseline: 2.9201x; 1.2626x over previous
#include <cuda_runtime.h>
#include <cuda_bf16.h>
#include <cstdint>
#include <cstddef>

// ---------------------------------------------------------------------------
#define NB    32
#define NPIX  4096
#define NTOK  (NB*NPIX)   // 131072
#define CIN   960
#define C3    96
#define NG    12
#define HW    64

typedef __nv_bfloat16 bf16;

// ---------------------------------------------------------------------------
// Scratch (device globals)
// ---------------------------------------------------------------------------
__device__ bf16  g_multi[(size_t)NB * 288 * NPIX];     // [b][ch][n] bf16 (75 MB)
__device__ bf16  g_att  [(size_t)NB * NPIX * C3];      // [b][n][ch] bf16 (25 MB) - token-major!
__device__ bf16  g_wqkv [C3 * CIN];
__device__ bf16  g_wproj[CIN * C3];
__device__ float g_vkp  [NB * NG * 4 * 72];            // vk partials (4 pixel chunks)

// ---------------------------------------------------------------------------
// K0: weight conversion fp32 -> bf16
// ---------------------------------------------------------------------------
__global__ void prep_weights(const float* __restrict__ qkv_w,
                             const float* __restrict__ proj_w) {
    int i = blockIdx.x * 256 + threadIdx.x;
    if (i < C3 * CIN) {
        g_wqkv[i]  = __float2bfloat16(qkv_w[i]);
        g_wproj[i] = __float2bfloat16(proj_w[i]);
    }
}

// ---------------------------------------------------------------------------
// mma.sync m16n8k16 bf16 helper
// ---------------------------------------------------------------------------
__device__ __forceinline__ void mma_bf16(float* c, const uint32_t* a, const uint32_t* b) {
    asm volatile(
        "mma.sync.aligned.m16n8k16.row.col.f32.bf16.bf16.f32 "
        "{%0,%1,%2,%3}, {%4,%5,%6,%7}, {%8,%9}, {%0,%1,%2,%3};\n"
        : "+f"(c[0]), "+f"(c[1]), "+f"(c[2]), "+f"(c[3])
        : "r"(a[0]), "r"(a[1]), "r"(a[2]), "r"(a[3]), "r"(b[0]), "r"(b[1]));
}

// ---------------------------------------------------------------------------
// K1: qkv GEMM (M=131072, N=96, K=960) with FUSED LayerNorm (stats + apply).
// ---------------------------------------------------------------------------
__global__ void __launch_bounds__(256) qkv_gemm_kernel(
    const float* __restrict__ x1, const float* __restrict__ x2, const float* __restrict__ x3,
    const float* __restrict__ g1, const float* __restrict__ b1,
    const float* __restrict__ g2, const float* __restrict__ b2,
    const float* __restrict__ g3, const float* __restrict__ b3) {
    __shared__ union {
        struct { bf16 A[128][40]; bf16 W[96][40]; } s;   // 17920 B
        bf16 C[96][136];                                  // 26112 B
    } sm;
    __shared__ float st[128][6];   // mean[3], rstd[3] per token
    const int tid  = threadIdx.x;
    const int warp = tid >> 5, lane = tid & 31;
    const int warpM = warp & 3, warpN = warp >> 2;
    const int g = lane >> 2, tg = lane & 3;
    const int token0 = blockIdx.x * 128;

    // ---- Pass 1: LN stats (streams the tile from DRAM; warms L2) ----
    {
        const float* xs[3] = {x1, x2, x3};
        const int    Cs[3] = {192, 256, 512};
        for (int t = warp; t < 128; t += 8) {
            int token = token0 + t;
            #pragma unroll
            for (int s = 0; s < 3; s++) {
                const float* p = xs[s] + (size_t)token * Cs[s];
                float sum = 0.f, sq = 0.f;
                for (int c = lane; c < Cs[s]; c += 32) { float v = p[c]; sum += v; sq += v * v; }
                #pragma unroll
                for (int off = 16; off > 0; off >>= 1) {
                    sum += __shfl_xor_sync(0xffffffffu, sum, off);
                    sq  += __shfl_xor_sync(0xffffffffu, sq,  off);
                }
                if (lane == 0) {
                    float m   = sum / (float)Cs[s];
                    float var = sq / (float)Cs[s] - m * m;
                    st[t][s]     = m;
                    st[t][3 + s] = rsqrtf(var + 1e-6f);
                }
            }
        }
    }
    __syncthreads();

    float acc[2][6][4];
    #pragma unroll
    for (int mr = 0; mr < 2; mr++)
        #pragma unroll
        for (int nb = 0; nb < 6; nb++)
            #pragma unroll
            for (int q = 0; q < 4; q++) acc[mr][nb][q] = 0.f;

    for (int kt = 0; kt < 30; kt++) {
        const int k0 = kt * 32;
        int seg, cbase, Csz; const float *xp, *gp, *bp;
        if (k0 < 192)      { seg = 0; cbase = 0;   Csz = 192; xp = x1; gp = g1; bp = b1; }
        else if (k0 < 448) { seg = 1; cbase = 192; Csz = 256; xp = x2; gp = g2; bp = b2; }
        else               { seg = 2; cbase = 448; Csz = 512; xp = x3; gp = g3; bp = b3; }
        __syncthreads();
        #pragma unroll
        for (int l = 0; l < 4; l++) {
            int fid = tid + l * 256;
            int row = fid >> 3, q4 = fid & 7;
            int token = token0 + row;
            int cl = k0 - cbase + q4 * 4;
            float4 xv = *reinterpret_cast<const float4*>(xp + (size_t)token * Csz + cl);
            float4 gv = *reinterpret_cast<const float4*>(gp + cl);
            float4 bv = *reinterpret_cast<const float4*>(bp + cl);
            float m = st[row][seg];
            float r = st[row][3 + seg];
            float f0 = (xv.x - m) * (r * gv.x) + bv.x;
            float f1 = (xv.y - m) * (r * gv.y) + bv.y;
            float f2 = (xv.z - m) * (r * gv.z) + bv.z;
            float f3 = (xv.w - m) * (r * gv.w) + bv.w;
            __nv_bfloat162 p0 = __floats2bfloat162_rn(f0, f1);
            __nv_bfloat162 p1 = __floats2bfloat162_rn(f2, f3);
            uint2 u = make_uint2(*reinterpret_cast<uint32_t*>(&p0),
                                 *reinterpret_cast<uint32_t*>(&p1));
            *reinterpret_cast<uint2*>(&sm.s.A[row][q4 * 4]) = u;
        }
        for (int idx = tid; idx < 384; idx += 256) {
            int o = idx >> 2, kq = idx & 3;
            uint4 w = *reinterpret_cast<const uint4*>(g_wqkv + (size_t)o * 960 + k0 + kq * 8);
            *reinterpret_cast<uint4*>(&sm.s.W[o][kq * 8]) = w;
        }
        __syncthreads();
        #pragma unroll
        for (int ks = 0; ks < 32; ks += 16) {
            uint32_t afr[2][4], bfr[6][2];
            #pragma unroll
            for (int mr = 0; mr < 2; mr++) {
                int r0 = warpM * 32 + mr * 16;
                afr[mr][0] = *reinterpret_cast<const uint32_t*>(&sm.s.A[r0 + g    ][ks + tg * 2    ]);
                afr[mr][1] = *reinterpret_cast<const uint32_t*>(&sm.s.A[r0 + g + 8][ks + tg * 2    ]);
                afr[mr][2] = *reinterpret_cast<const uint32_t*>(&sm.s.A[r0 + g    ][ks + tg * 2 + 8]);
                afr[mr][3] = *reinterpret_cast<const uint32_t*>(&sm.s.A[r0 + g + 8][ks + tg * 2 + 8]);
            }
            #pragma unroll
            for (int nb = 0; nb < 6; nb++) {
                int o = warpN * 48 + nb * 8 + g;
                bfr[nb][0] = *reinterpret_cast<const uint32_t*>(&sm.s.W[o][ks + tg * 2    ]);
                bfr[nb][1] = *reinterpret_cast<const uint32_t*>(&sm.s.W[o][ks + tg * 2 + 8]);
            }
            #pragma unroll
            for (int mr = 0; mr < 2; mr++)
                #pragma unroll
                for (int nb = 0; nb < 6; nb++)
                    mma_bf16(acc[mr][nb], afr[mr], bfr[nb]);
        }
    }
    __syncthreads();
    #pragma unroll
    for (int mr = 0; mr < 2; mr++)
        #pragma unroll
        for (int nb = 0; nb < 6; nb++) {
            int oo = warpN * 48 + nb * 8 + tg * 2;
            int t0 = warpM * 32 + mr * 16 + g;
            sm.C[oo    ][t0    ] = __float2bfloat16(acc[mr][nb][0]);
            sm.C[oo + 1][t0    ] = __float2bfloat16(acc[mr][nb][1]);
            sm.C[oo    ][t0 + 8] = __float2bfloat16(acc[mr][nb][2]);
            sm.C[oo + 1][t0 + 8] = __float2bfloat16(acc[mr][nb][3]);
        }
    __syncthreads();
    const int bb = token0 >> 12;
    const int n0 = token0 & (NPIX - 1);
    #pragma unroll
    for (int i = 0; i < 6; i++) {
        int idx = tid + i * 256;
        int o = idx >> 4, q = idx & 15;
        uint4 v = *reinterpret_cast<const uint4*>(&sm.C[o][q * 8]);
        *reinterpret_cast<uint4*>(g_multi + ((size_t)bb * 288 + o) * NPIX + n0 + q * 8) = v;
    }
}

// ---------------------------------------------------------------------------
// K2: MERGED dw3+pw3 and dw5+pw5. Each thread computes a 1x4 pixel strip:
// 5x8 register window per channel -> 2.5x fewer LDS than per-pixel.
// ---------------------------------------------------------------------------
__global__ void __launch_bounds__(256) dwpw_merged_kernel(
        const float* __restrict__ dw3_w, const float* __restrict__ pw3_w,
        const float* __restrict__ dw5_w, const float* __restrict__ pw5_w) {
    constexpr int T = 36;
    __shared__ float sin_[8][T][T];
    __shared__ float wd3[8][9], wd5[8][25];
    __shared__ float wp3[8][8], wp5[8][8];   // [in][out]
    const int b = blockIdx.z, g = blockIdx.y, tile = blockIdx.x;
    const int ty0 = (tile >> 1) * 32, tx0 = (tile & 1) * 32;
    const int tid = threadIdx.x;
    const bf16* src = g_multi + ((size_t)b * 288 + g * 8) * NPIX;

    for (int idx = tid; idx < 8 * T * T; idx += 256) {
        int ch = idx / (T * T); int rem = idx - ch * T * T;
        int yy = rem / T, xx = rem - yy * T;
        int gy = ty0 + yy - 2, gx = tx0 + xx - 2;
        float v = 0.f;
        if (gy >= 0 && gy < HW && gx >= 0 && gx < HW)
            v = __bfloat162float(src[ch * NPIX + gy * HW + gx]);
        sin_[ch][yy][xx] = v;
    }
    if (tid < 72)  { int ch = tid / 9,  kk = tid % 9;  wd3[ch][kk] = dw3_w[(g * 8 + ch) * 9  + kk]; }
    else if (tid < 136) { int t = tid - 72; wp3[t & 7][t >> 3] = pw3_w[(g * 8 + (t >> 3)) * 8 + (t & 7)]; }
    else if (tid < 200) { int t = tid - 136; wp5[t & 7][t >> 3] = pw5_w[(g * 8 + (t >> 3)) * 8 + (t & 7)]; }
    for (int t = tid; t < 200; t += 256) {
        int ch = t / 25, kk = t % 25;
        wd5[ch][kk] = dw5_w[(g * 8 + ch) * 25 + kk];
    }
    __syncthreads();

    const int py  = tid >> 3;          // 0..31
    const int px0 = (tid & 7) * 4;     // 0,4,...,28
    float o3[4][8], o5[4][8];
    #pragma unroll
    for (int j = 0; j < 4; j++)
        #pragma unroll
        for (int o = 0; o < 8; o++) { o3[j][o] = 0.f; o5[j][o] = 0.f; }

    #pragma unroll 1
    for (int ch = 0; ch < 8; ch++) {
        float w[5][8];
        #pragma unroll
        for (int r = 0; r < 5; r++) {
            float4 a = *reinterpret_cast<const float4*>(&sin_[ch][py + r][px0]);
            float4 c = *reinterpret_cast<const float4*>(&sin_[ch][py + r][px0 + 4]);
            w[r][0] = a.x; w[r][1] = a.y; w[r][2] = a.z; w[r][3] = a.w;
            w[r][4] = c.x; w[r][5] = c.y; w[r][6] = c.z; w[r][7] = c.w;
        }
        #pragma unroll
        for (int j = 0; j < 4; j++) {
            float s5 = 0.f;
            #pragma unroll
            for (int r = 0; r < 5; r++)
                #pragma unroll
                for (int c = 0; c < 5; c++)
                    s5 = fmaf(w[r][c + j], wd5[ch][r * 5 + c], s5);
            float s3 = 0.f;
            #pragma unroll
            for (int r = 0; r < 3; r++)
                #pragma unroll
                for (int c = 0; c < 3; c++)
                    s3 = fmaf(w[r + 1][c + j + 1], wd3[ch][r * 3 + c], s3);
            #pragma unroll
            for (int o = 0; o < 8; o++) {
                o3[j][o] = fmaf(wp3[ch][o], s3, o3[j][o]);
                o5[j][o] = fmaf(wp5[ch][o], s5, o5[j][o]);
            }
        }
    }
    bf16* dst3 = g_multi + ((size_t)b * 288 +  96 + g * 8) * NPIX;
    bf16* dst5 = g_multi + ((size_t)b * 288 + 192 + g * 8) * NPIX;
    int n = (ty0 + py) * HW + (tx0 + px0);
    #pragma unroll
    for (int o = 0; o < 8; o++) {
        __nv_bfloat162 a0 = __floats2bfloat162_rn(o3[0][o], o3[1][o]);
        __nv_bfloat162 a1 = __floats2bfloat162_rn(o3[2][o], o3[3][o]);
        uint2 u3 = make_uint2(*reinterpret_cast<uint32_t*>(&a0), *reinterpret_cast<uint32_t*>(&a1));
        *reinterpret_cast<uint2*>(dst3 + o * NPIX + n) = u3;
        __nv_bfloat162 b0 = __floats2bfloat162_rn(o5[0][o], o5[1][o]);
        __nv_bfloat162 b1 = __floats2bfloat162_rn(o5[2][o], o5[3][o]);
        uint2 u5 = make_uint2(*reinterpret_cast<uint32_t*>(&b0), *reinterpret_cast<uint32_t*>(&b1));
        *reinterpret_cast<uint2*>(dst5 + o * NPIX + n) = u5;
    }
}

// ---------------------------------------------------------------------------
// K3a: vk partials per (b, g, pixel-chunk). Deterministic (no atomics).
// ---------------------------------------------------------------------------
__global__ void __launch_bounds__(256) attn_vk_kernel() {
    const int g = blockIdx.x, b = blockIdx.y, z = blockIdx.z;
    const int tid = threadIdx.x, lane = tid & 31, wrp = tid >> 5;
    const bf16* mg = g_multi + ((size_t)b * 288 + g * 24) * NPIX;

    float acc[9][8];
    #pragma unroll
    for (int d = 0; d < 9; d++)
        #pragma unroll
        for (int e = 0; e < 8; e++) acc[d][e] = 0.f;

    #pragma unroll
    for (int it = 0; it < 2; it++) {
        int n = z * 1024 + it * 512 + tid * 2;
        float k0[8], k1[8], v0[8], v1[8];
        #pragma unroll
        for (int e = 0; e < 8; e++) {
            __nv_bfloat162 kp = *reinterpret_cast<const __nv_bfloat162*>(mg + (8 + e) * NPIX + n);
            k0[e] = fmaxf(__bfloat162float(kp.x), 0.f);
            k1[e] = fmaxf(__bfloat162float(kp.y), 0.f);
        }
        #pragma unroll
        for (int d = 0; d < 8; d++) {
            __nv_bfloat162 vp = *reinterpret_cast<const __nv_bfloat162*>(mg + (16 + d) * NPIX + n);
            v0[d] = __bfloat162float(vp.x);
            v1[d] = __bfloat162float(vp.y);
        }
        #pragma unroll
        for (int d = 0; d < 8; d++)
            #pragma unroll
            for (int e = 0; e < 8; e++)
                acc[d][e] = fmaf(v1[d], k1[e], fmaf(v0[d], k0[e], acc[d][e]));
        #pragma unroll
        for (int e = 0; e < 8; e++) acc[8][e] += k0[e] + k1[e];
    }
    __shared__ float red[8][72];
    #pragma unroll
    for (int d = 0; d < 9; d++)
        #pragma unroll
        for (int e = 0; e < 8; e++) {
            float s = acc[d][e];
            #pragma unroll
            for (int off = 16; off > 0; off >>= 1) s += __shfl_xor_sync(0xffffffffu, s, off);
            if (lane == 0) red[wrp][d * 8 + e] = s;
        }
    __syncthreads();
    if (tid < 72) {
        float s = 0.f;
        #pragma unroll
        for (int w = 0; w < 8; w++) s += red[w][tid];
        g_vkp[(((size_t)b * NG + g) * 4 + z) * 72 + tid] = s;
    }
}

// ---------------------------------------------------------------------------
// K3b: apply: att[n][g*8+d] = (sum_e vk[d][e] relu(q[e][n])) / den.
// Writes token-major g_att (one uint4 per pixel).
// ---------------------------------------------------------------------------
__global__ void __launch_bounds__(256) attn_apply_kernel() {
    const int g = blockIdx.x, b = blockIdx.y, z = blockIdx.z;
    const int tid = threadIdx.x;
    __shared__ float vk[72];
    if (tid < 72) {
        const float* p = g_vkp + ((size_t)b * NG + g) * 4 * 72 + tid;
        vk[tid] = p[0] + p[72] + p[144] + p[216];
    }
    __syncthreads();
    const bf16* mg = g_multi + ((size_t)b * 288 + g * 24) * NPIX;
    bf16* ab = g_att + ((size_t)b * NPIX) * C3 + g * 8;

    #pragma unroll
    for (int it = 0; it < 4; it++) {
        int n = z * 2048 + it * 512 + tid * 2;
        float n0[8], n1[8];
        #pragma unroll
        for (int d = 0; d < 8; d++) { n0[d] = 0.f; n1[d] = 0.f; }
        float d0 = 1e-15f, d1 = 1e-15f;
        #pragma unroll
        for (int e = 0; e < 8; e++) {
            __nv_bfloat162 qp = *reinterpret_cast<const __nv_bfloat162*>(mg + e * NPIX + n);
            float q0 = fmaxf(__bfloat162float(qp.x), 0.f);
            float q1 = fmaxf(__bfloat162float(qp.y), 0.f);
            #pragma unroll
            for (int d = 0; d < 8; d++) {
                n0[d] = fmaf(vk[d * 8 + e], q0, n0[d]);
                n1[d] = fmaf(vk[d * 8 + e], q1, n1[d]);
            }
            d0 = fmaf(vk[64 + e], q0, d0);
            d1 = fmaf(vk[64 + e], q1, d1);
        }
        float i0 = 1.f / d0, i1 = 1.f / d1;
        uint4 u0, u1;
        {
            __nv_bfloat162 p0 = __floats2bfloat162_rn(n0[0] * i0, n0[1] * i0);
            __nv_bfloat162 p1 = __floats2bfloat162_rn(n0[2] * i0, n0[3] * i0);
            __nv_bfloat162 p2 = __floats2bfloat162_rn(n0[4] * i0, n0[5] * i0);
            __nv_bfloat162 p3 = __floats2bfloat162_rn(n0[6] * i0, n0[7] * i0);
            u0 = make_uint4(*reinterpret_cast<uint32_t*>(&p0), *reinterpret_cast<uint32_t*>(&p1),
                            *reinterpret_cast<uint32_t*>(&p2), *reinterpret_cast<uint32_t*>(&p3));
        }
        {
            __nv_bfloat162 p0 = __floats2bfloat162_rn(n1[0] * i1, n1[1] * i1);
            __nv_bfloat162 p1 = __floats2bfloat162_rn(n1[2] * i1, n1[3] * i1);
            __nv_bfloat162 p2 = __floats2bfloat162_rn(n1[4] * i1, n1[5] * i1);
            __nv_bfloat162 p3 = __floats2bfloat162_rn(n1[6] * i1, n1[7] * i1);
            u1 = make_uint4(*reinterpret_cast<uint32_t*>(&p0), *reinterpret_cast<uint32_t*>(&p1),
                            *reinterpret_cast<uint32_t*>(&p2), *reinterpret_cast<uint32_t*>(&p3));
        }
        *reinterpret_cast<uint4*>(ab + (size_t)n * C3) = u0;
        *reinterpret_cast<uint4*>(ab + (size_t)(n + 1) * C3) = u1;
    }
}

// ---------------------------------------------------------------------------
// K4: proj GEMM (M=131072, N=960, K=96) bf16 mma + BN + residual + split.
// A (att) now token-major: direct coalesced loads, single K-resident smem,
// one sync, 6 mma k-steps, conflict-free fragment reads (stride 104).
// ---------------------------------------------------------------------------
__global__ void __launch_bounds__(256) proj_gemm_kernel(
    const float* __restrict__ bn_g, const float* __restrict__ bn_b,
    const float* __restrict__ bn_m, const float* __restrict__ bn_v,
    const float* __restrict__ x1, const float* __restrict__ x2, const float* __restrict__ x3,
    float* __restrict__ out) {
    __shared__ union {
        struct { bf16 A[128][104]; bf16 W[96][104]; } s;  // 46592 B
        bf16 C[128][104];
    } sm;
    __shared__ float scv[96], shv[96];
    const int tid  = threadIdx.x;
    const int warp = tid >> 5, lane = tid & 31;
    const int warpM = warp & 3, warpN = warp >> 2;
    const int g = lane >> 2, tg = lane & 3;
    const int o0 = blockIdx.x * 96;
    const int token0 = blockIdx.y * 128;
    const int bb = token0 >> 12;
    const int n0 = token0 & (NPIX - 1);

    if (tid < 96) {
        int o = o0 + tid;
        float sc = bn_g[o] * rsqrtf(bn_v[o] + 1e-5f);
        scv[tid] = sc;
        shv[tid] = bn_b[o] - bn_m[o] * sc;
    }
    // W tile: 96 x 96
    for (int idx = tid; idx < 96 * 12; idx += 256) {
        int o = idx / 12, kq = idx % 12;
        uint4 w = *reinterpret_cast<const uint4*>(g_wproj + (size_t)(o0 + o) * 96 + kq * 8);
        *reinterpret_cast<uint4*>(&sm.s.W[o][kq * 8]) = w;
    }
    // A tile: 128 tokens x 96 ch, contiguous rows
    const bf16* attb = g_att + ((size_t)bb * NPIX + n0) * C3;
    #pragma unroll
    for (int l = 0; l < 6; l++) {
        int idx = tid + l * 256;
        int row = idx / 12, q = idx % 12;
        uint4 v = *reinterpret_cast<const uint4*>(attb + (size_t)row * C3 + q * 8);
        *reinterpret_cast<uint4*>(&sm.s.A[row][q * 8]) = v;
    }
    __syncthreads();

    float acc[2][6][4];
    #pragma unroll
    for (int mr = 0; mr < 2; mr++)
        #pragma unroll
        for (int nb = 0; nb < 6; nb++)
            #pragma unroll
            for (int q = 0; q < 4; q++) acc[mr][nb][q] = 0.f;

    #pragma unroll
    for (int ks = 0; ks < 96; ks += 16) {
        uint32_t afr[2][4], bfr[6][2];
        #pragma unroll
        for (int mr = 0; mr < 2; mr++) {
            int r0 = warpM * 32 + mr * 16;
            afr[mr][0] = *reinterpret_cast<const uint32_t*>(&sm.s.A[r0 + g    ][ks + tg * 2    ]);
            afr[mr][1] = *reinterpret_cast<const uint32_t*>(&sm.s.A[r0 + g + 8][ks + tg * 2    ]);
            afr[mr][2] = *reinterpret_cast<const uint32_t*>(&sm.s.A[r0 + g    ][ks + tg * 2 + 8]);
            afr[mr][3] = *reinterpret_cast<const uint32_t*>(&sm.s.A[r0 + g + 8][ks + tg * 2 + 8]);
        }
        #pragma unroll
        for (int nb = 0; nb < 6; nb++) {
            int o = warpN * 48 + nb * 8 + g;
            bfr[nb][0] = *reinterpret_cast<const uint32_t*>(&sm.s.W[o][ks + tg * 2    ]);
            bfr[nb][1] = *reinterpret_cast<const uint32_t*>(&sm.s.W[o][ks + tg * 2 + 8]);
        }
        #pragma unroll
        for (int mr = 0; mr < 2; mr++)
            #pragma unroll
            for (int nb = 0; nb < 6; nb++)
                mma_bf16(acc[mr][nb], afr[mr], bfr[nb]);
    }
    __syncthreads();
    #pragma unroll
    for (int mr = 0; mr < 2; mr++)
        #pragma unroll
        for (int nb = 0; nb < 6; nb++) {
            int oo = warpN * 48 + nb * 8 + tg * 2;
            int t0 = warpM * 32 + mr * 16 + g;
            __nv_bfloat162 p0 = __floats2bfloat162_rn(acc[mr][nb][0], acc[mr][nb][1]);
            __nv_bfloat162 p1 = __floats2bfloat162_rn(acc[mr][nb][2], acc[mr][nb][3]);
            *reinterpret_cast<uint32_t*>(&sm.C[t0    ][oo]) = *reinterpret_cast<uint32_t*>(&p0);
            *reinterpret_cast<uint32_t*>(&sm.C[t0 + 8][oo]) = *reinterpret_cast<uint32_t*>(&p1);
        }
    __syncthreads();
    #pragma unroll
    for (int i = 0; i < 12; i++) {
        int idx = tid + i * 256;
        int tl = idx / 24, qo = idx % 24;
        int o_g = o0 + qo * 4;
        int token = token0 + tl;
        const float* xr; size_t obase; int Csz, cl;
        if (o_g < 192)      { xr = x1; obase = 0;                  Csz = 192; cl = o_g; }
        else if (o_g < 448) { xr = x2; obase = (size_t)NTOK * 192; Csz = 256; cl = o_g - 192; }
        else                { xr = x3; obase = (size_t)NTOK * 448; Csz = 512; cl = o_g - 448; }
        size_t base = (size_t)token * Csz + cl;
        float4 xv = *reinterpret_cast<const float4*>(xr + base);
        uint2 cu = *reinterpret_cast<const uint2*>(&sm.C[tl][qo * 4]);
        const bf16* ch4 = reinterpret_cast<const bf16*>(&cu);
        int ol = qo * 4;
        float4 ov;
        ov.x = scv[ol    ] * __bfloat162float(ch4[0]) + shv[ol    ] + xv.x;
        ov.y = scv[ol + 1] * __bfloat162float(ch4[1]) + shv[ol + 1] + xv.y;
        ov.z = scv[ol + 2] * __bfloat162float(ch4[2]) + shv[ol + 2] + xv.z;
        ov.w = scv[ol + 3] * __bfloat162float(ch4[3]) + shv[ol + 3] + xv.w;
        *reinterpret_cast<float4*>(out + obase + base) = ov;
    }
}

// ---------------------------------------------------------------------------
// Launch
// ---------------------------------------------------------------------------
extern "C" void kernel_launch(void* const* d_in, const int* in_sizes, int n_in,
                              void* d_out, int out_size) {
    (void)out_size;
    const float *x1 = 0, *x2 = 0, *x3 = 0;
    const float *g1 = 0, *b1 = 0, *g2 = 0, *b2 = 0, *g3 = 0, *b3 = 0;
    const float *qkv_w = 0, *dw3 = 0, *pw3 = 0, *dw5 = 0, *pw5 = 0, *proj_w = 0;
    const float *bn_g = 0, *bn_b = 0, *bn_m = 0, *bn_v = 0;
    int c192 = 0, c256 = 0, c512 = 0, cW = 0, c768 = 0, c960 = 0;
    for (int i = 0; i < n_in; i++) {
        const float* p = (const float*)d_in[i];
        switch (in_sizes[i]) {
            case 25165824: x1 = p; break;
            case 33554432: x2 = p; break;
            case 67108864: x3 = p; break;
            case 192: (c192++ ? b1 : g1) = p; break;
            case 256: (c256++ ? b2 : g2) = p; break;
            case 512: (c512++ ? b3 : g3) = p; break;
            case 92160: (cW++ ? proj_w : qkv_w) = p; break;
            case 864:  dw3 = p; break;
            case 2400: dw5 = p; break;
            case 768: (c768++ ? pw5 : pw3) = p; break;
            case 960: {
                if      (c960 == 0) bn_g = p;
                else if (c960 == 1) bn_b = p;
                else if (c960 == 2) bn_m = p;
                else                bn_v = p;
                c960++;
            } break;
            default: break;
        }
    }
    float* out = (float*)d_out;

    prep_weights<<<(C3 * CIN + 255) / 256, 256>>>(qkv_w, proj_w);
    qkv_gemm_kernel<<<NTOK / 128, 256>>>(x1, x2, x3, g1, b1, g2, b2, g3, b3);
    dwpw_merged_kernel<<<dim3(4, NG, NB), 256>>>(dw3, pw3, dw5, pw5);
    attn_vk_kernel<<<dim3(NG, NB, 4), 256>>>();
    attn_apply_kernel<<<dim3(NG, NB, 2), 256>>>();
    proj_gemm_kernel<<<dim3(10, NTOK / 128), 256>>>(bn_g, bn_b, bn_m, bn_v,
                                                    x1, x2, x3, out);
}

// round 6
// speedup vs baseline: 3.1360x; 1.0739x over previous
#include <cuda_runtime.h>
#include <cuda_bf16.h>
#include <cstdint>
#include <cstddef>

// ---------------------------------------------------------------------------
#define NB    32
#define NPIX  4096
#define NTOK  (NB*NPIX)   // 131072
#define CIN   960
#define C3    96
#define NG    12
#define HW    64

typedef __nv_bfloat16 bf16;

// ---------------------------------------------------------------------------
// Scratch (device globals)
// ---------------------------------------------------------------------------
__device__ bf16  g_xn   [(size_t)NTOK * CIN];          // LN'd x, [token][960] bf16 (251 MB)
__device__ bf16  g_multi[(size_t)NB * 288 * NPIX];     // [b][ch][n] bf16 (75 MB)
__device__ bf16  g_att  [(size_t)NB * NPIX * C3];      // [b][n][ch] bf16 (25 MB) token-major
__device__ bf16  g_wqkv [C3 * CIN];
__device__ bf16  g_wproj[CIN * C3];
__device__ float g_vkp  [NB * NG * 8 * 72];            // vk partials (8 pixel chunks)

// ---------------------------------------------------------------------------
// K0: weight conversion fp32 -> bf16
// ---------------------------------------------------------------------------
__global__ void prep_weights(const float* __restrict__ qkv_w,
                             const float* __restrict__ proj_w) {
    int i = blockIdx.x * 256 + threadIdx.x;
    if (i < C3 * CIN) {
        g_wqkv[i]  = __float2bfloat16(qkv_w[i]);
        g_wproj[i] = __float2bfloat16(proj_w[i]);
    }
}

// ---------------------------------------------------------------------------
// K1: LayerNorm, warp-per-token, fully register-resident.
// Reads x once (fp32), writes LN'd bf16 into g_xn[token][960].
// ---------------------------------------------------------------------------
template<int CSZ>
__device__ __forceinline__ void norm_seg(const float* __restrict__ p,
                                         const float* __restrict__ gw,
                                         const float* __restrict__ bw,
                                         bf16* __restrict__ dst, int lane) {
    constexpr int NQ = CSZ / 4;            // quads per row: 48, 64, 128
    constexpr int NI = (NQ + 31) / 32;     // per-lane iterations: 2, 2, 4
    float4 v[NI];
    float sum = 0.f, sq = 0.f;
    #pragma unroll
    for (int i = 0; i < NI; i++) {
        int q = lane + i * 32;
        if ((NQ % 32 == 0) || q < NQ) {
            v[i] = *reinterpret_cast<const float4*>(p + q * 4);
            sum += v[i].x + v[i].y + v[i].z + v[i].w;
            sq  += v[i].x * v[i].x + v[i].y * v[i].y + v[i].z * v[i].z + v[i].w * v[i].w;
        }
    }
    #pragma unroll
    for (int off = 16; off > 0; off >>= 1) {
        sum += __shfl_xor_sync(0xffffffffu, sum, off);
        sq  += __shfl_xor_sync(0xffffffffu, sq,  off);
    }
    float m = sum / (float)CSZ;
    float r = rsqrtf(sq / (float)CSZ - m * m + 1e-6f);
    #pragma unroll
    for (int i = 0; i < NI; i++) {
        int q = lane + i * 32;
        if ((NQ % 32 == 0) || q < NQ) {
            float4 gv = *reinterpret_cast<const float4*>(gw + q * 4);
            float4 bv = *reinterpret_cast<const float4*>(bw + q * 4);
            float f0 = (v[i].x - m) * (r * gv.x) + bv.x;
            float f1 = (v[i].y - m) * (r * gv.y) + bv.y;
            float f2 = (v[i].z - m) * (r * gv.z) + bv.z;
            float f3 = (v[i].w - m) * (r * gv.w) + bv.w;
            __nv_bfloat162 p0 = __floats2bfloat162_rn(f0, f1);
            __nv_bfloat162 p1 = __floats2bfloat162_rn(f2, f3);
            uint2 u = make_uint2(*reinterpret_cast<uint32_t*>(&p0),
                                 *reinterpret_cast<uint32_t*>(&p1));
            *reinterpret_cast<uint2*>(dst + q * 4) = u;
        }
    }
}

__global__ void __launch_bounds__(256) norm_kernel(
    const float* __restrict__ x1, const float* __restrict__ x2, const float* __restrict__ x3,
    const float* __restrict__ g1, const float* __restrict__ b1,
    const float* __restrict__ g2, const float* __restrict__ b2,
    const float* __restrict__ g3, const float* __restrict__ b3) {
    int t = (blockIdx.x * 256 + threadIdx.x) >> 5;
    int lane = threadIdx.x & 31;
    bf16* dst = g_xn + (size_t)t * CIN;
    norm_seg<192>(x1 + (size_t)t * 192, g1, b1, dst,       lane);
    norm_seg<256>(x2 + (size_t)t * 256, g2, b2, dst + 192, lane);
    norm_seg<512>(x3 + (size_t)t * 512, g3, b3, dst + 448, lane);
}

// ---------------------------------------------------------------------------
// mma.sync m16n8k16 bf16 helper
// ---------------------------------------------------------------------------
__device__ __forceinline__ void mma_bf16(float* c, const uint32_t* a, const uint32_t* b) {
    asm volatile(
        "mma.sync.aligned.m16n8k16.row.col.f32.bf16.bf16.f32 "
        "{%0,%1,%2,%3}, {%4,%5,%6,%7}, {%8,%9}, {%0,%1,%2,%3};\n"
        : "+f"(c[0]), "+f"(c[1]), "+f"(c[2]), "+f"(c[3])
        : "r"(a[0]), "r"(a[1]), "r"(a[2]), "r"(a[3]), "r"(b[0]), "r"(b[1]));
}

// ---------------------------------------------------------------------------
// K2: qkv GEMM (M=131072, N=96, K=960), bf16 A from g_xn (contiguous rows).
// ---------------------------------------------------------------------------
__global__ void __launch_bounds__(256) qkv_gemm_kernel() {
    __shared__ union {
        struct { bf16 A[128][40]; bf16 W[96][40]; } s;   // 17920 B
        bf16 C[96][136];                                  // 26112 B
    } sm;
    const int tid  = threadIdx.x;
    const int warp = tid >> 5, lane = tid & 31;
    const int warpM = warp & 3, warpN = warp >> 2;
    const int g = lane >> 2, tg = lane & 3;
    const int token0 = blockIdx.x * 128;
    const bf16* An = g_xn + (size_t)token0 * CIN;

    float acc[2][6][4];
    #pragma unroll
    for (int mr = 0; mr < 2; mr++)
        #pragma unroll
        for (int nb = 0; nb < 6; nb++)
            #pragma unroll
            for (int q = 0; q < 4; q++) acc[mr][nb][q] = 0.f;

    for (int kt = 0; kt < 30; kt++) {
        const int k0 = kt * 32;
        __syncthreads();
        // A tile: 128 x 32 bf16, contiguous uint4 loads
        #pragma unroll
        for (int l = 0; l < 2; l++) {
            int idx = tid + l * 256;             // 512 uint4
            int row = idx >> 2, q = idx & 3;
            uint4 v = *reinterpret_cast<const uint4*>(An + (size_t)row * CIN + k0 + q * 8);
            *reinterpret_cast<uint4*>(&sm.s.A[row][q * 8]) = v;
        }
        // W tile: 96 x 32
        for (int idx = tid; idx < 384; idx += 256) {
            int o = idx >> 2, kq = idx & 3;
            uint4 w = *reinterpret_cast<const uint4*>(g_wqkv + (size_t)o * CIN + k0 + kq * 8);
            *reinterpret_cast<uint4*>(&sm.s.W[o][kq * 8]) = w;
        }
        __syncthreads();
        #pragma unroll
        for (int ks = 0; ks < 32; ks += 16) {
            uint32_t afr[2][4], bfr[6][2];
            #pragma unroll
            for (int mr = 0; mr < 2; mr++) {
                int r0 = warpM * 32 + mr * 16;
                afr[mr][0] = *reinterpret_cast<const uint32_t*>(&sm.s.A[r0 + g    ][ks + tg * 2    ]);
                afr[mr][1] = *reinterpret_cast<const uint32_t*>(&sm.s.A[r0 + g + 8][ks + tg * 2    ]);
                afr[mr][2] = *reinterpret_cast<const uint32_t*>(&sm.s.A[r0 + g    ][ks + tg * 2 + 8]);
                afr[mr][3] = *reinterpret_cast<const uint32_t*>(&sm.s.A[r0 + g + 8][ks + tg * 2 + 8]);
            }
            #pragma unroll
            for (int nb = 0; nb < 6; nb++) {
                int o = warpN * 48 + nb * 8 + g;
                bfr[nb][0] = *reinterpret_cast<const uint32_t*>(&sm.s.W[o][ks + tg * 2    ]);
                bfr[nb][1] = *reinterpret_cast<const uint32_t*>(&sm.s.W[o][ks + tg * 2 + 8]);
            }
            #pragma unroll
            for (int mr = 0; mr < 2; mr++)
                #pragma unroll
                for (int nb = 0; nb < 6; nb++)
                    mma_bf16(acc[mr][nb], afr[mr], bfr[nb]);
        }
    }
    __syncthreads();
    #pragma unroll
    for (int mr = 0; mr < 2; mr++)
        #pragma unroll
        for (int nb = 0; nb < 6; nb++) {
            int oo = warpN * 48 + nb * 8 + tg * 2;
            int t0 = warpM * 32 + mr * 16 + g;
            sm.C[oo    ][t0    ] = __float2bfloat16(acc[mr][nb][0]);
            sm.C[oo + 1][t0    ] = __float2bfloat16(acc[mr][nb][1]);
            sm.C[oo    ][t0 + 8] = __float2bfloat16(acc[mr][nb][2]);
            sm.C[oo + 1][t0 + 8] = __float2bfloat16(acc[mr][nb][3]);
        }
    __syncthreads();
    const int bb = token0 >> 12;
    const int n0 = token0 & (NPIX - 1);
    #pragma unroll
    for (int i = 0; i < 6; i++) {
        int idx = tid + i * 256;
        int o = idx >> 4, q = idx & 15;
        uint4 v = *reinterpret_cast<const uint4*>(&sm.C[o][q * 8]);
        *reinterpret_cast<uint4*>(g_multi + ((size_t)bb * 288 + o) * NPIX + n0 + q * 8) = v;
    }
}

// ---------------------------------------------------------------------------
// K3: MERGED dw3+pw3 and dw5+pw5. 1x4 pixel strip per thread.
// ---------------------------------------------------------------------------
__global__ void __launch_bounds__(256) dwpw_merged_kernel(
        const float* __restrict__ dw3_w, const float* __restrict__ pw3_w,
        const float* __restrict__ dw5_w, const float* __restrict__ pw5_w) {
    constexpr int T = 36;
    __shared__ float sin_[8][T][T];
    __shared__ float wd3[8][9], wd5[8][25];
    __shared__ float wp3[8][8], wp5[8][8];   // [in][out]
    const int b = blockIdx.z, g = blockIdx.y, tile = blockIdx.x;
    const int ty0 = (tile >> 1) * 32, tx0 = (tile & 1) * 32;
    const int tid = threadIdx.x;
    const bf16* src = g_multi + ((size_t)b * 288 + g * 8) * NPIX;

    for (int idx = tid; idx < 8 * T * T; idx += 256) {
        int ch = idx / (T * T); int rem = idx - ch * T * T;
        int yy = rem / T, xx = rem - yy * T;
        int gy = ty0 + yy - 2, gx = tx0 + xx - 2;
        float v = 0.f;
        if (gy >= 0 && gy < HW && gx >= 0 && gx < HW)
            v = __bfloat162float(src[ch * NPIX + gy * HW + gx]);
        sin_[ch][yy][xx] = v;
    }
    if (tid < 72)  { int ch = tid / 9,  kk = tid % 9;  wd3[ch][kk] = dw3_w[(g * 8 + ch) * 9  + kk]; }
    else if (tid < 136) { int t = tid - 72; wp3[t & 7][t >> 3] = pw3_w[(g * 8 + (t >> 3)) * 8 + (t & 7)]; }
    else if (tid < 200) { int t = tid - 136; wp5[t & 7][t >> 3] = pw5_w[(g * 8 + (t >> 3)) * 8 + (t & 7)]; }
    for (int t = tid; t < 200; t += 256) {
        int ch = t / 25, kk = t % 25;
        wd5[ch][kk] = dw5_w[(g * 8 + ch) * 25 + kk];
    }
    __syncthreads();

    const int py  = tid >> 3;
    const int px0 = (tid & 7) * 4;
    float o3[4][8], o5[4][8];
    #pragma unroll
    for (int j = 0; j < 4; j++)
        #pragma unroll
        for (int o = 0; o < 8; o++) { o3[j][o] = 0.f; o5[j][o] = 0.f; }

    #pragma unroll 1
    for (int ch = 0; ch < 8; ch++) {
        float w[5][8];
        #pragma unroll
        for (int r = 0; r < 5; r++) {
            float4 a = *reinterpret_cast<const float4*>(&sin_[ch][py + r][px0]);
            float4 c = *reinterpret_cast<const float4*>(&sin_[ch][py + r][px0 + 4]);
            w[r][0] = a.x; w[r][1] = a.y; w[r][2] = a.z; w[r][3] = a.w;
            w[r][4] = c.x; w[r][5] = c.y; w[r][6] = c.z; w[r][7] = c.w;
        }
        #pragma unroll
        for (int j = 0; j < 4; j++) {
            float s5 = 0.f;
            #pragma unroll
            for (int r = 0; r < 5; r++)
                #pragma unroll
                for (int c = 0; c < 5; c++)
                    s5 = fmaf(w[r][c + j], wd5[ch][r * 5 + c], s5);
            float s3 = 0.f;
            #pragma unroll
            for (int r = 0; r < 3; r++)
                #pragma unroll
                for (int c = 0; c < 3; c++)
                    s3 = fmaf(w[r + 1][c + j + 1], wd3[ch][r * 3 + c], s3);
            #pragma unroll
            for (int o = 0; o < 8; o++) {
                o3[j][o] = fmaf(wp3[ch][o], s3, o3[j][o]);
                o5[j][o] = fmaf(wp5[ch][o], s5, o5[j][o]);
            }
        }
    }
    bf16* dst3 = g_multi + ((size_t)b * 288 +  96 + g * 8) * NPIX;
    bf16* dst5 = g_multi + ((size_t)b * 288 + 192 + g * 8) * NPIX;
    int n = (ty0 + py) * HW + (tx0 + px0);
    #pragma unroll
    for (int o = 0; o < 8; o++) {
        __nv_bfloat162 a0 = __floats2bfloat162_rn(o3[0][o], o3[1][o]);
        __nv_bfloat162 a1 = __floats2bfloat162_rn(o3[2][o], o3[3][o]);
        uint2 u3 = make_uint2(*reinterpret_cast<uint32_t*>(&a0), *reinterpret_cast<uint32_t*>(&a1));
        *reinterpret_cast<uint2*>(dst3 + o * NPIX + n) = u3;
        __nv_bfloat162 b0 = __floats2bfloat162_rn(o5[0][o], o5[1][o]);
        __nv_bfloat162 b1 = __floats2bfloat162_rn(o5[2][o], o5[3][o]);
        uint2 u5 = make_uint2(*reinterpret_cast<uint32_t*>(&b0), *reinterpret_cast<uint32_t*>(&b1));
        *reinterpret_cast<uint2*>(dst5 + o * NPIX + n) = u5;
    }
}

// ---------------------------------------------------------------------------
// K4a: vk partials per (b, g, pixel-chunk z of 8). Deterministic.
// ---------------------------------------------------------------------------
__global__ void __launch_bounds__(256) attn_vk_kernel() {
    const int g = blockIdx.x, b = blockIdx.y, z = blockIdx.z;
    const int tid = threadIdx.x, lane = tid & 31, wrp = tid >> 5;
    const bf16* mg = g_multi + ((size_t)b * 288 + g * 24) * NPIX;

    float acc[9][8];
    #pragma unroll
    for (int d = 0; d < 9; d++)
        #pragma unroll
        for (int e = 0; e < 8; e++) acc[d][e] = 0.f;

    {
        int n = z * 512 + tid * 2;
        float k0[8], k1[8], v0[8], v1[8];
        #pragma unroll
        for (int e = 0; e < 8; e++) {
            __nv_bfloat162 kp = *reinterpret_cast<const __nv_bfloat162*>(mg + (8 + e) * NPIX + n);
            k0[e] = fmaxf(__bfloat162float(kp.x), 0.f);
            k1[e] = fmaxf(__bfloat162float(kp.y), 0.f);
        }
        #pragma unroll
        for (int d = 0; d < 8; d++) {
            __nv_bfloat162 vp = *reinterpret_cast<const __nv_bfloat162*>(mg + (16 + d) * NPIX + n);
            v0[d] = __bfloat162float(vp.x);
            v1[d] = __bfloat162float(vp.y);
        }
        #pragma unroll
        for (int d = 0; d < 8; d++)
            #pragma unroll
            for (int e = 0; e < 8; e++)
                acc[d][e] = fmaf(v1[d], k1[e], fmaf(v0[d], k0[e], acc[d][e]));
        #pragma unroll
        for (int e = 0; e < 8; e++) acc[8][e] += k0[e] + k1[e];
    }
    __shared__ float red[8][72];
    #pragma unroll
    for (int d = 0; d < 9; d++)
        #pragma unroll
        for (int e = 0; e < 8; e++) {
            float s = acc[d][e];
            #pragma unroll
            for (int off = 16; off > 0; off >>= 1) s += __shfl_xor_sync(0xffffffffu, s, off);
            if (lane == 0) red[wrp][d * 8 + e] = s;
        }
    __syncthreads();
    if (tid < 72) {
        float s = 0.f;
        #pragma unroll
        for (int w = 0; w < 8; w++) s += red[w][tid];
        g_vkp[(((size_t)b * NG + g) * 8 + z) * 72 + tid] = s;
    }
}

// ---------------------------------------------------------------------------
// K4b: apply, writes token-major g_att (one uint4 per pixel).
// ---------------------------------------------------------------------------
__global__ void __launch_bounds__(256) attn_apply_kernel() {
    const int g = blockIdx.x, b = blockIdx.y, z = blockIdx.z;
    const int tid = threadIdx.x;
    __shared__ float vk[72];
    if (tid < 72) {
        const float* p = g_vkp + ((size_t)b * NG + g) * 8 * 72 + tid;
        float s = 0.f;
        #pragma unroll
        for (int w = 0; w < 8; w++) s += p[w * 72];
        vk[tid] = s;
    }
    __syncthreads();
    const bf16* mg = g_multi + ((size_t)b * 288 + g * 24) * NPIX;
    bf16* ab = g_att + ((size_t)b * NPIX) * C3 + g * 8;

    #pragma unroll
    for (int it = 0; it < 4; it++) {
        int n = z * 2048 + it * 512 + tid * 2;
        float n0[8], n1[8];
        #pragma unroll
        for (int d = 0; d < 8; d++) { n0[d] = 0.f; n1[d] = 0.f; }
        float d0 = 1e-15f, d1 = 1e-15f;
        #pragma unroll
        for (int e = 0; e < 8; e++) {
            __nv_bfloat162 qp = *reinterpret_cast<const __nv_bfloat162*>(mg + e * NPIX + n);
            float q0 = fmaxf(__bfloat162float(qp.x), 0.f);
            float q1 = fmaxf(__bfloat162float(qp.y), 0.f);
            #pragma unroll
            for (int d = 0; d < 8; d++) {
                n0[d] = fmaf(vk[d * 8 + e], q0, n0[d]);
                n1[d] = fmaf(vk[d * 8 + e], q1, n1[d]);
            }
            d0 = fmaf(vk[64 + e], q0, d0);
            d1 = fmaf(vk[64 + e], q1, d1);
        }
        float i0 = 1.f / d0, i1 = 1.f / d1;
        uint4 u0, u1;
        {
            __nv_bfloat162 p0 = __floats2bfloat162_rn(n0[0] * i0, n0[1] * i0);
            __nv_bfloat162 p1 = __floats2bfloat162_rn(n0[2] * i0, n0[3] * i0);
            __nv_bfloat162 p2 = __floats2bfloat162_rn(n0[4] * i0, n0[5] * i0);
            __nv_bfloat162 p3 = __floats2bfloat162_rn(n0[6] * i0, n0[7] * i0);
            u0 = make_uint4(*reinterpret_cast<uint32_t*>(&p0), *reinterpret_cast<uint32_t*>(&p1),
                            *reinterpret_cast<uint32_t*>(&p2), *reinterpret_cast<uint32_t*>(&p3));
        }
        {
            __nv_bfloat162 p0 = __floats2bfloat162_rn(n1[0] * i1, n1[1] * i1);
            __nv_bfloat162 p1 = __floats2bfloat162_rn(n1[2] * i1, n1[3] * i1);
            __nv_bfloat162 p2 = __floats2bfloat162_rn(n1[4] * i1, n1[5] * i1);
            __nv_bfloat162 p3 = __floats2bfloat162_rn(n1[6] * i1, n1[7] * i1);
            u1 = make_uint4(*reinterpret_cast<uint32_t*>(&p0), *reinterpret_cast<uint32_t*>(&p1),
                            *reinterpret_cast<uint32_t*>(&p2), *reinterpret_cast<uint32_t*>(&p3));
        }
        *reinterpret_cast<uint4*>(ab + (size_t)n * C3) = u0;
        *reinterpret_cast<uint4*>(ab + (size_t)(n + 1) * C3) = u1;
    }
}

// ---------------------------------------------------------------------------
// K5: proj GEMM (M=131072, N=960, K=96) + BN + residual + split.
// ---------------------------------------------------------------------------
__global__ void __launch_bounds__(256) proj_gemm_kernel(
    const float* __restrict__ bn_g, const float* __restrict__ bn_b,
    const float* __restrict__ bn_m, const float* __restrict__ bn_v,
    const float* __restrict__ x1, const float* __restrict__ x2, const float* __restrict__ x3,
    float* __restrict__ out) {
    __shared__ union {
        struct { bf16 A[128][104]; bf16 W[96][104]; } s;  // 46592 B
        bf16 C[128][104];
    } sm;
    __shared__ float scv[96], shv[96];
    const int tid  = threadIdx.x;
    const int warp = tid >> 5, lane = tid & 31;
    const int warpM = warp & 3, warpN = warp >> 2;
    const int g = lane >> 2, tg = lane & 3;
    const int o0 = blockIdx.x * 96;
    const int token0 = blockIdx.y * 128;
    const int bb = token0 >> 12;
    const int n0 = token0 & (NPIX - 1);

    if (tid < 96) {
        int o = o0 + tid;
        float sc = bn_g[o] * rsqrtf(bn_v[o] + 1e-5f);
        scv[tid] = sc;
        shv[tid] = bn_b[o] - bn_m[o] * sc;
    }
    for (int idx = tid; idx < 96 * 12; idx += 256) {
        int o = idx / 12, kq = idx % 12;
        uint4 w = *reinterpret_cast<const uint4*>(g_wproj + (size_t)(o0 + o) * 96 + kq * 8);
        *reinterpret_cast<uint4*>(&sm.s.W[o][kq * 8]) = w;
    }
    const bf16* attb = g_att + ((size_t)bb * NPIX + n0) * C3;
    #pragma unroll
    for (int l = 0; l < 6; l++) {
        int idx = tid + l * 256;
        int row = idx / 12, q = idx % 12;
        uint4 v = *reinterpret_cast<const uint4*>(attb + (size_t)row * C3 + q * 8);
        *reinterpret_cast<uint4*>(&sm.s.A[row][q * 8]) = v;
    }
    __syncthreads();

    float acc[2][6][4];
    #pragma unroll
    for (int mr = 0; mr < 2; mr++)
        #pragma unroll
        for (int nb = 0; nb < 6; nb++)
            #pragma unroll
            for (int q = 0; q < 4; q++) acc[mr][nb][q] = 0.f;

    #pragma unroll
    for (int ks = 0; ks < 96; ks += 16) {
        uint32_t afr[2][4], bfr[6][2];
        #pragma unroll
        for (int mr = 0; mr < 2; mr++) {
            int r0 = warpM * 32 + mr * 16;
            afr[mr][0] = *reinterpret_cast<const uint32_t*>(&sm.s.A[r0 + g    ][ks + tg * 2    ]);
            afr[mr][1] = *reinterpret_cast<const uint32_t*>(&sm.s.A[r0 + g + 8][ks + tg * 2    ]);
            afr[mr][2] = *reinterpret_cast<const uint32_t*>(&sm.s.A[r0 + g    ][ks + tg * 2 + 8]);
            afr[mr][3] = *reinterpret_cast<const uint32_t*>(&sm.s.A[r0 + g + 8][ks + tg * 2 + 8]);
        }
        #pragma unroll
        for (int nb = 0; nb < 6; nb++) {
            int o = warpN * 48 + nb * 8 + g;
            bfr[nb][0] = *reinterpret_cast<const uint32_t*>(&sm.s.W[o][ks + tg * 2    ]);
            bfr[nb][1] = *reinterpret_cast<const uint32_t*>(&sm.s.W[o][ks + tg * 2 + 8]);
        }
        #pragma unroll
        for (int mr = 0; mr < 2; mr++)
            #pragma unroll
            for (int nb = 0; nb < 6; nb++)
                mma_bf16(acc[mr][nb], afr[mr], bfr[nb]);
    }
    __syncthreads();
    #pragma unroll
    for (int mr = 0; mr < 2; mr++)
        #pragma unroll
        for (int nb = 0; nb < 6; nb++) {
            int oo = warpN * 48 + nb * 8 + tg * 2;
            int t0 = warpM * 32 + mr * 16 + g;
            __nv_bfloat162 p0 = __floats2bfloat162_rn(acc[mr][nb][0], acc[mr][nb][1]);
            __nv_bfloat162 p1 = __floats2bfloat162_rn(acc[mr][nb][2], acc[mr][nb][3]);
            *reinterpret_cast<uint32_t*>(&sm.C[t0    ][oo]) = *reinterpret_cast<uint32_t*>(&p0);
            *reinterpret_cast<uint32_t*>(&sm.C[t0 + 8][oo]) = *reinterpret_cast<uint32_t*>(&p1);
        }
    __syncthreads();
    #pragma unroll
    for (int i = 0; i < 12; i++) {
        int idx = tid + i * 256;
        int tl = idx / 24, qo = idx % 24;
        int o_g = o0 + qo * 4;
        int token = token0 + tl;
        const float* xr; size_t obase; int Csz, cl;
        if (o_g < 192)      { xr = x1; obase = 0;                  Csz = 192; cl = o_g; }
        else if (o_g < 448) { xr = x2; obase = (size_t)NTOK * 192; Csz = 256; cl = o_g - 192; }
        else                { xr = x3; obase = (size_t)NTOK * 448; Csz = 512; cl = o_g - 448; }
        size_t base = (size_t)token * Csz + cl;
        float4 xv = *reinterpret_cast<const float4*>(xr + base);
        uint2 cu = *reinterpret_cast<const uint2*>(&sm.C[tl][qo * 4]);
        const bf16* ch4 = reinterpret_cast<const bf16*>(&cu);
        int ol = qo * 4;
        float4 ov;
        ov.x = scv[ol    ] * __bfloat162float(ch4[0]) + shv[ol    ] + xv.x;
        ov.y = scv[ol + 1] * __bfloat162float(ch4[1]) + shv[ol + 1] + xv.y;
        ov.z = scv[ol + 2] * __bfloat162float(ch4[2]) + shv[ol + 2] + xv.z;
        ov.w = scv[ol + 3] * __bfloat162float(ch4[3]) + shv[ol + 3] + xv.w;
        *reinterpret_cast<float4*>(out + obase + base) = ov;
    }
}

// ---------------------------------------------------------------------------
// Launch
// ---------------------------------------------------------------------------
extern "C" void kernel_launch(void* const* d_in, const int* in_sizes, int n_in,
                              void* d_out, int out_size) {
    (void)out_size;
    const float *x1 = 0, *x2 = 0, *x3 = 0;
    const float *g1 = 0, *b1 = 0, *g2 = 0, *b2 = 0, *g3 = 0, *b3 = 0;
    const float *qkv_w = 0, *dw3 = 0, *pw3 = 0, *dw5 = 0, *pw5 = 0, *proj_w = 0;
    const float *bn_g = 0, *bn_b = 0, *bn_m = 0, *bn_v = 0;
    int c192 = 0, c256 = 0, c512 = 0, cW = 0, c768 = 0, c960 = 0;
    for (int i = 0; i < n_in; i++) {
        const float* p = (const float*)d_in[i];
        switch (in_sizes[i]) {
            case 25165824: x1 = p; break;
            case 33554432: x2 = p; break;
            case 67108864: x3 = p; break;
            case 192: (c192++ ? b1 : g1) = p; break;
            case 256: (c256++ ? b2 : g2) = p; break;
            case 512: (c512++ ? b3 : g3) = p; break;
            case 92160: (cW++ ? proj_w : qkv_w) = p; break;
            case 864:  dw3 = p; break;
            case 2400: dw5 = p; break;
            case 768: (c768++ ? pw5 : pw3) = p; break;
            case 960: {
                if      (c960 == 0) bn_g = p;
                else if (c960 == 1) bn_b = p;
                else if (c960 == 2) bn_m = p;
                else                bn_v = p;
                c960++;
            } break;
            default: break;
        }
    }
    float* out = (float*)d_out;

    prep_weights<<<(C3 * CIN + 255) / 256, 256>>>(qkv_w, proj_w);
    norm_kernel<<<NTOK / 8, 256>>>(x1, x2, x3, g1, b1, g2, b2, g3, b3);
    qkv_gemm_kernel<<<NTOK / 128, 256>>>();
    dwpw_merged_kernel<<<dim3(4, NG, NB), 256>>>(dw3, pw3, dw5, pw5);
    attn_vk_kernel<<<dim3(NG, NB, 8), 256>>>();
    attn_apply_kernel<<<dim3(NG, NB, 2), 256>>>();
    proj_gemm_kernel<<<dim3(10, NTOK / 128), 256>>>(bn_g, bn_b, bn_m, bn_v,
                                                    x1, x2, x3, out);
}